// round 4
// baseline (speedup 1.0000x reference)
#include <cuda_runtime.h>
#include <cuda_bf16.h>
#include <cstdint>
#include <cstddef>

#define N_NODES 20000
#define N_EDGES 320000
#define M_PAD   20224          // 79 * 256
#define F1 1152
#define F2 576
#define F3 288

#define KCAT1 (6 * F1)         // 6912
#define KCAT2 (5 * F1)         // 5760
#define KCAT3 (5 * F2)         // 2880
#define N1PAD 1152             // 9 * 128
#define N2PAD 640              // 5 * 128
#define N3PAD 384              // 3 * 128

// ---------------- scratch (device globals; allocation-free) ----------------
__device__ float g_bufA[N_NODES * F1];
__device__ float g_bufB[N_NODES * F1];
__device__ float g_bufC[N_NODES * F1];
__device__ float g_acc1[N_NODES * F1];
__device__ float g_acc2[N_NODES * F2];

__device__ __nv_bfloat16 g_Ahi[(size_t)M_PAD * KCAT1];
__device__ __nv_bfloat16 g_Alo[(size_t)M_PAD * KCAT1];
__device__ __nv_bfloat16 g_W1h[(size_t)N1PAD * KCAT1];
__device__ __nv_bfloat16 g_W1l[(size_t)N1PAD * KCAT1];
__device__ __nv_bfloat16 g_W2h[(size_t)N2PAD * KCAT2];
__device__ __nv_bfloat16 g_W2l[(size_t)N2PAD * KCAT2];
__device__ __nv_bfloat16 g_W3h[(size_t)N3PAD * KCAT3];
__device__ __nv_bfloat16 g_W3l[(size_t)N3PAD * KCAT3];

__device__ int   g_deg[N_NODES];
__device__ int   g_fill[N_NODES];
__device__ int   g_rowptr[N_NODES + 1];
__device__ int   g_colS[N_EDGES];
__device__ float g_dis[N_NODES];

// ---------------- PTX helpers (base sm_103 target only) ----------------
__device__ __forceinline__ uint32_t smem_u32(const void* p) {
    uint32_t a;
    asm("{ .reg .u64 t; cvta.to.shared.u64 t, %1; cvt.u32.u64 %0, t; }" : "=r"(a) : "l"(p));
    return a;
}

#define CP_ASYNC16(dst, src) \
    asm volatile("cp.async.cg.shared.global [%0], [%1], 16;" :: "r"(dst), "l"(src) : "memory")
#define CP_COMMIT() asm volatile("cp.async.commit_group;" ::: "memory")
#define CP_WAIT2()  asm volatile("cp.async.wait_group 2;" ::: "memory")

#define LDMATRIX_X4(r0, r1, r2, r3, addr) \
    asm volatile("ldmatrix.sync.aligned.m8n8.x4.shared.b16 {%0,%1,%2,%3}, [%4];" \
                 : "=r"(r0), "=r"(r1), "=r"(r2), "=r"(r3) : "r"(addr))

#define MMA_BF16(d, a, b) \
    asm volatile("mma.sync.aligned.m16n8k16.row.col.f32.bf16.bf16.f32 " \
                 "{%0,%1,%2,%3}, {%4,%5,%6,%7}, {%8,%9}, {%0,%1,%2,%3};" \
                 : "+f"((d)[0]), "+f"((d)[1]), "+f"((d)[2]), "+f"((d)[3]) \
                 : "r"((a)[0]), "r"((a)[1]), "r"((a)[2]), "r"((a)[3]), \
                   "r"((b)[0]), "r"((b)[1]))

// ---------------- graph setup ----------------
__global__ void zero_counts_kernel() {
    int i = blockIdx.x * blockDim.x + threadIdx.x;
    if (i < N_NODES) { g_deg[i] = 0; g_fill[i] = 0; }
}
__global__ void hist_kernel(const int* __restrict__ row, const int* __restrict__ col) {
    int e = blockIdx.x * blockDim.x + threadIdx.x;
    if (e < N_EDGES) {
        int r = row[e];
        if (r != col[e]) atomicAdd(&g_deg[r], 1);
    }
}
__global__ void scan_kernel() {
    __shared__ int sums[1024];
    int t = threadIdx.x;
    const int CHUNK = (N_NODES + 1023) / 1024;
    int lo = t * CHUNK, hi = lo + CHUNK;
    if (hi > N_NODES) hi = N_NODES;
    int s = 0;
    for (int i = lo; i < hi; i++) s += g_deg[i];
    sums[t] = s;
    __syncthreads();
    for (int off = 1; off < 1024; off <<= 1) {
        int v = (t >= off) ? sums[t - off] : 0;
        __syncthreads();
        sums[t] += v;
        __syncthreads();
    }
    int run = (t == 0) ? 0 : sums[t - 1];
    for (int i = lo; i < hi; i++) { g_rowptr[i] = run; run += g_deg[i]; }
    if (t == 1023) g_rowptr[N_NODES] = sums[1023];
}
__global__ void dis_kernel() {
    int i = blockIdx.x * blockDim.x + threadIdx.x;
    if (i < N_NODES) {
        int d = g_deg[i];
        g_dis[i] = (d > 0) ? rsqrtf((float)d) : 0.0f;
    }
}
__global__ void scatter_kernel(const int* __restrict__ row, const int* __restrict__ col) {
    int e = blockIdx.x * blockDim.x + threadIdx.x;
    if (e < N_EDGES) {
        int r = row[e], c = col[e];
        if (r != c) {
            int pos = g_rowptr[r] + atomicAdd(&g_fill[r], 1);
            g_colS[pos] = c;
        }
    }
}

// ---------------- split helpers ----------------
__device__ __forceinline__ void split1(float v, __nv_bfloat16& h, __nv_bfloat16& l) {
    h = __float2bfloat16(v);
    l = __float2bfloat16(v - __bfloat162float(h));
}

// convert Tx0 (fp32 [M x F]) into cat slice; zero pad rows
__global__ void convert_split_kernel(const float* __restrict__ src, int F,
                                     __nv_bfloat16* __restrict__ hi,
                                     __nv_bfloat16* __restrict__ lo,
                                     int ldCat, int colOff) {
    int total = M_PAD * F;
    for (int idx = blockIdx.x * blockDim.x + threadIdx.x; idx < total;
         idx += gridDim.x * blockDim.x) {
        int r = idx / F, c = idx - r * F;
        float v = (r < N_NODES) ? src[(size_t)r * F + c] : 0.0f;
        __nv_bfloat16 h, l;
        split1(v, h, l);
        size_t o = (size_t)r * ldCat + colOff + c;
        hi[o] = h; lo[o] = l;
    }
}

// weight transpose + split: W [Kcat x N] fp32 -> WT hi/lo [Npad x Kcat] bf16
__global__ void wsplit_kernel(const float* __restrict__ W, int Kcat, int N, int Npad,
                              __nv_bfloat16* __restrict__ hi,
                              __nv_bfloat16* __restrict__ lo) {
    __shared__ float tile[32][33];
    int k0 = blockIdx.x * 32, n0 = blockIdx.y * 32;
    int tx = threadIdx.x, ty = threadIdx.y;   // (32, 8)
#pragma unroll
    for (int r = 0; r < 32; r += 8) {
        int kk = k0 + ty + r, nn = n0 + tx;
        tile[ty + r][tx] = (kk < Kcat && nn < N) ? W[(size_t)kk * N + nn] : 0.0f;
    }
    __syncthreads();
#pragma unroll
    for (int r = 0; r < 32; r += 8) {
        int nn = n0 + ty + r, kk = k0 + tx;
        if (nn < Npad && kk < Kcat) {
            float v = tile[tx][ty + r];
            __nv_bfloat16 h, l;
            split1(v, h, l);
            hi[(size_t)nn * Kcat + kk] = h;
            lo[(size_t)nn * Kcat + kk] = l;
        }
    }
}

// ---------------- propagation with fused bf16 split of the output ----------
// out = alpha * (L~ t) - sub ; also writes hi/lo split into cat slice.
template <int F>
__global__ void prop_kernel(const float* __restrict__ t,
                            const float* __restrict__ sub,
                            float* __restrict__ out,
                            __nv_bfloat16* __restrict__ hi,
                            __nv_bfloat16* __restrict__ lo,
                            int ldCat, int colOff, float alpha) {
    constexpr int F4 = F / 4;
    constexpr int NF = (F4 + 127) / 128;
    int i = blockIdx.x;
    int tid = threadIdx.x;
    bool real = (i < N_NODES);
    int s0 = real ? g_rowptr[i] : 0;
    int s1 = real ? g_rowptr[i + 1] : 0;

    float ax[NF], ay[NF], az[NF], aw[NF];
#pragma unroll
    for (int j = 0; j < NF; j++) { ax[j] = 0.f; ay[j] = 0.f; az[j] = 0.f; aw[j] = 0.f; }

    int e = s0;
    for (; e + 2 <= s1; e += 2) {
        int c0 = g_colS[e], c1 = g_colS[e + 1];
        float w0 = g_dis[c0], w1 = g_dis[c1];
        const float4* t0 = reinterpret_cast<const float4*>(t) + (size_t)c0 * F4;
        const float4* t1 = reinterpret_cast<const float4*>(t) + (size_t)c1 * F4;
#pragma unroll
        for (int j = 0; j < NF; j++) {
            int f = tid + j * 128;
            if ((F4 % 128 == 0) || f < F4) {
                float4 v0 = t0[f];
                float4 v1 = t1[f];
                ax[j] += w0 * v0.x + w1 * v1.x;
                ay[j] += w0 * v0.y + w1 * v1.y;
                az[j] += w0 * v0.z + w1 * v1.z;
                aw[j] += w0 * v0.w + w1 * v1.w;
            }
        }
    }
    if (e < s1) {
        int c = g_colS[e];
        float s = g_dis[c];
        const float4* tr = reinterpret_cast<const float4*>(t) + (size_t)c * F4;
#pragma unroll
        for (int j = 0; j < NF; j++) {
            int f = tid + j * 128;
            if ((F4 % 128 == 0) || f < F4) {
                float4 v = tr[f];
                ax[j] += s * v.x; ay[j] += s * v.y;
                az[j] += s * v.z; aw[j] += s * v.w;
            }
        }
    }

    float sc = real ? (-alpha * g_dis[i]) : 0.0f;
    float4* orow = real ? (reinterpret_cast<float4*>(out) + (size_t)i * F4) : nullptr;
    const float4* srow = (real && sub)
        ? (reinterpret_cast<const float4*>(sub) + (size_t)i * F4) : nullptr;
#pragma unroll
    for (int j = 0; j < NF; j++) {
        int f = tid + j * 128;
        if ((F4 % 128 == 0) || f < F4) {
            float4 r;
            r.x = sc * ax[j]; r.y = sc * ay[j]; r.z = sc * az[j]; r.w = sc * aw[j];
            if (srow) {
                float4 sv = srow[f];
                r.x -= sv.x; r.y -= sv.y; r.z -= sv.z; r.w -= sv.w;
            }
            if (orow) orow[f] = r;
            __nv_bfloat16 hx, lx, hy, ly, hz, lz, hw, lw;
            split1(r.x, hx, lx); split1(r.y, hy, ly);
            split1(r.z, hz, lz); split1(r.w, hw, lw);
            size_t o = (size_t)i * ldCat + colOff + (size_t)f * 4;
            __nv_bfloat162* hp = reinterpret_cast<__nv_bfloat162*>(hi + o);
            __nv_bfloat162* lp = reinterpret_cast<__nv_bfloat162*>(lo + o);
            hp[0] = __nv_bfloat162(hx, hy); hp[1] = __nv_bfloat162(hz, hw);
            lp[0] = __nv_bfloat162(lx, ly); lp[1] = __nv_bfloat162(lz, lw);
        }
    }
}

// ---------------- mma.sync GEMM (256x128 CTA, 64x64/warp) ----------------
// C[M x N] = relu( A x B^T + bias ), 3-pass bf16 split in one long K loop.
// A: [M_PAD x Kcat] bf16 row-major.  B: [Npad x Kcat] bf16 row-major (= W^T).
#define GSTAGES 4
#define GBK     32
#define ROWB    80                        // padded SMEM row bytes (stride 5 in 16B units)
#define ATILE_B (256 * ROWB)              // 20480
#define BTILE_B (128 * ROWB)              // 10240
#define STG_B   (ATILE_B + BTILE_B)       // 30720
#define SMEM_TOTAL_GEMM (GSTAGES * STG_B) // 122880

__global__ void __launch_bounds__(256, 1)
gemm_mma_kernel(const __nv_bfloat16* __restrict__ Ahi, const __nv_bfloat16* __restrict__ Alo,
                const __nv_bfloat16* __restrict__ Bhi, const __nv_bfloat16* __restrict__ Blo,
                const float* __restrict__ bias, float* __restrict__ C,
                int N, int Kcat) {
    extern __shared__ char smem[];
    uint32_t sb = smem_u32(smem);
    int tid = threadIdx.x;
    int lane = tid & 31;
    int wid = tid >> 5;
    int bm = blockIdx.y * 256;
    int bn = blockIdx.x * 128;

    const int kt = Kcat / GBK;         // k-tiles per pass
    const int NIT = 3 * kt;

    int wm = (wid & 3) * 64;           // warp M offset (4 warps cover 256)
    int wn = (wid >> 2) * 64;          // warp N offset (2 warps cover 128)

    float d[4][8][4];
#pragma unroll
    for (int i = 0; i < 4; i++)
#pragma unroll
        for (int j = 0; j < 8; j++)
#pragma unroll
            for (int q = 0; q < 4; q++) d[i][j][q] = 0.f;

    auto issue = [&](int it) {
        int pass = it / kt;
        int kk = (it - pass * kt) * GBK;
        const __nv_bfloat16* Ab = (pass == 1) ? Alo : Ahi;
        const __nv_bfloat16* Bb = (pass == 2) ? Blo : Bhi;
        int s = it & (GSTAGES - 1);
        uint32_t sA = sb + s * STG_B;
        uint32_t sB = sA + ATILE_B;
        const char* gA = (const char*)(Ab + (size_t)bm * Kcat + kk);
        const char* gB = (const char*)(Bb + (size_t)bn * Kcat + kk);
        size_t ld = (size_t)Kcat * 2;
        // A: 256 rows x 64B = 1024 16B-chunks; 4 per thread
#pragma unroll
        for (int i = 0; i < 4; i++) {
            int v = tid + i * 256;
            int r = v >> 2, p = v & 3;
            CP_ASYNC16(sA + r * ROWB + p * 16, gA + (size_t)r * ld + p * 16);
        }
        // B: 128 rows x 64B = 512 chunks; 2 per thread
#pragma unroll
        for (int i = 0; i < 2; i++) {
            int v = tid + i * 256;
            int r = v >> 2, p = v & 3;
            CP_ASYNC16(sB + r * ROWB + p * 16, gB + (size_t)r * ld + p * 16);
        }
    };

    // prologue: fill 3 stages
#pragma unroll
    for (int it = 0; it < GSTAGES - 1; it++) { issue(it); CP_COMMIT(); }

    int lrow = lane & 15;              // ldmatrix row within 16
    int lcol = (lane >> 4) * 8;        // ldmatrix k-half select

    for (int it = 0; it < NIT; ++it) {
        CP_WAIT2();
        __syncthreads();

        int s = it & (GSTAGES - 1);
        uint32_t sA = sb + s * STG_B;
        uint32_t sB = sA + ATILE_B;

#pragma unroll
        for (int ks = 0; ks < GBK; ks += 16) {
            uint32_t a[4][4], b[8][2];
#pragma unroll
            for (int i = 0; i < 4; i++) {
                uint32_t addr = sA + (wm + i * 16 + lrow) * ROWB + (ks + lcol) * 2;
                LDMATRIX_X4(a[i][0], a[i][1], a[i][2], a[i][3], addr);
            }
#pragma unroll
            for (int jp = 0; jp < 4; jp++) {
                uint32_t q0, q1, q2, q3;
                uint32_t addr = sB + (wn + jp * 16 + lrow) * ROWB + (ks + lcol) * 2;
                LDMATRIX_X4(q0, q1, q2, q3, addr);
                b[2 * jp][0] = q0; b[2 * jp][1] = q2;
                b[2 * jp + 1][0] = q1; b[2 * jp + 1][1] = q3;
            }
#pragma unroll
            for (int i = 0; i < 4; i++)
#pragma unroll
                for (int j = 0; j < 8; j++)
                    MMA_BF16(d[i][j], a[i], b[j]);
        }

        __syncthreads();
        if (it + GSTAGES - 1 < NIT) issue(it + GSTAGES - 1);
        CP_COMMIT();
    }

    // epilogue: bias + relu, fp32 writes
    int gr = lane >> 2;
    int gc = (lane & 3) * 2;
#pragma unroll
    for (int i = 0; i < 4; i++) {
#pragma unroll
        for (int j = 0; j < 8; j++) {
            int colb = bn + wn + j * 8 + gc;
            if (colb >= N) continue;
            float b0 = bias[colb], b1 = bias[colb + 1];
            int row0 = bm + wm + i * 16 + gr;
            if (row0 < N_NODES) {
                float2 v;
                v.x = fmaxf(d[i][j][0] + b0, 0.f);
                v.y = fmaxf(d[i][j][1] + b1, 0.f);
                *reinterpret_cast<float2*>(&C[(size_t)row0 * N + colb]) = v;
            }
            int row1 = row0 + 8;
            if (row1 < N_NODES) {
                float2 v;
                v.x = fmaxf(d[i][j][2] + b0, 0.f);
                v.y = fmaxf(d[i][j][3] + b1, 0.f);
                *reinterpret_cast<float2*>(&C[(size_t)row1 * N + colb]) = v;
            }
        }
    }
}

// ---------------- host orchestration ----------------
extern "C" void kernel_launch(void* const* d_in, const int* in_sizes, int n_in,
                              void* d_out, int out_size) {
    const float* x   = (const float*)d_in[0];
    const int*   row = (const int*)d_in[1];
    const int*   col = (const int*)d_in[2];
    const float* W1  = (const float*)d_in[3];
    const float* b1  = (const float*)d_in[4];
    const float* W2  = (const float*)d_in[5];
    const float* b2  = (const float*)d_in[6];
    const float* W3  = (const float*)d_in[7];
    const float* b3  = (const float*)d_in[8];
    float* out = (float*)d_out;

    float *bufA, *bufB, *bufC, *acc1, *acc2;
    __nv_bfloat16 *Ahi, *Alo, *W1h, *W1l, *W2h, *W2l, *W3h, *W3l;
    cudaGetSymbolAddress((void**)&bufA, g_bufA);
    cudaGetSymbolAddress((void**)&bufB, g_bufB);
    cudaGetSymbolAddress((void**)&bufC, g_bufC);
    cudaGetSymbolAddress((void**)&acc1, g_acc1);
    cudaGetSymbolAddress((void**)&acc2, g_acc2);
    cudaGetSymbolAddress((void**)&Ahi, g_Ahi);
    cudaGetSymbolAddress((void**)&Alo, g_Alo);
    cudaGetSymbolAddress((void**)&W1h, g_W1h);
    cudaGetSymbolAddress((void**)&W1l, g_W1l);
    cudaGetSymbolAddress((void**)&W2h, g_W2h);
    cudaGetSymbolAddress((void**)&W2l, g_W2l);
    cudaGetSymbolAddress((void**)&W3h, g_W3h);
    cudaGetSymbolAddress((void**)&W3l, g_W3l);

    cudaFuncSetAttribute(gemm_mma_kernel,
                         cudaFuncAttributeMaxDynamicSharedMemorySize, SMEM_TOTAL_GEMM);

    // ---- graph setup ----
    zero_counts_kernel<<<(N_NODES + 255) / 256, 256>>>();
    hist_kernel<<<(N_EDGES + 255) / 256, 256>>>(row, col);
    scan_kernel<<<1, 1024>>>();
    dis_kernel<<<(N_NODES + 255) / 256, 256>>>();
    scatter_kernel<<<(N_EDGES + 255) / 256, 256>>>(row, col);

    // ---- weight conversions ----
    {
        dim3 g1((KCAT1 + 31) / 32, (N1PAD + 31) / 32);
        wsplit_kernel<<<g1, dim3(32, 8)>>>(W1, KCAT1, F1, N1PAD, W1h, W1l);
        dim3 g2((KCAT2 + 31) / 32, (N2PAD + 31) / 32);
        wsplit_kernel<<<g2, dim3(32, 8)>>>(W2, KCAT2, F2, N2PAD, W2h, W2l);
        dim3 g3((KCAT3 + 31) / 32, (N3PAD + 31) / 32);
        wsplit_kernel<<<g3, dim3(32, 8)>>>(W3, KCAT3, F3, N3PAD, W3h, W3l);
    }

    // ================= Layer 1: 1152 -> 1152, K=6, Kcat=6912 =================
    convert_split_kernel<<<4096, 256>>>(x, F1, Ahi, Alo, KCAT1, 0);
    prop_kernel<F1><<<M_PAD, 128>>>(x,    nullptr, bufA, Ahi, Alo, KCAT1, 1 * F1, 1.0f);
    prop_kernel<F1><<<M_PAD, 128>>>(bufA, x,       bufB, Ahi, Alo, KCAT1, 2 * F1, 2.0f);
    prop_kernel<F1><<<M_PAD, 128>>>(bufB, bufA,    bufC, Ahi, Alo, KCAT1, 3 * F1, 2.0f);
    prop_kernel<F1><<<M_PAD, 128>>>(bufC, bufB,    bufA, Ahi, Alo, KCAT1, 4 * F1, 2.0f);
    prop_kernel<F1><<<M_PAD, 128>>>(bufA, bufC,    bufB, Ahi, Alo, KCAT1, 5 * F1, 2.0f);
    {
        dim3 grid(N1PAD / 128, M_PAD / 256);
        gemm_mma_kernel<<<grid, 256, SMEM_TOTAL_GEMM>>>(Ahi, Alo, W1h, W1l, b1, acc1, F1, KCAT1);
    }

    // ================= Layer 2: 1152 -> 576, K=5, Kcat=5760 =================
    convert_split_kernel<<<4096, 256>>>(acc1, F1, Ahi, Alo, KCAT2, 0);
    prop_kernel<F1><<<M_PAD, 128>>>(acc1, nullptr, bufA, Ahi, Alo, KCAT2, 1 * F1, 1.0f);
    prop_kernel<F1><<<M_PAD, 128>>>(bufA, acc1,    bufB, Ahi, Alo, KCAT2, 2 * F1, 2.0f);
    prop_kernel<F1><<<M_PAD, 128>>>(bufB, bufA,    bufC, Ahi, Alo, KCAT2, 3 * F1, 2.0f);
    prop_kernel<F1><<<M_PAD, 128>>>(bufC, bufB,    bufA, Ahi, Alo, KCAT2, 4 * F1, 2.0f);
    {
        dim3 grid(N2PAD / 128, M_PAD / 256);
        gemm_mma_kernel<<<grid, 256, SMEM_TOTAL_GEMM>>>(Ahi, Alo, W2h, W2l, b2, acc2, F2, KCAT2);
    }

    // ================= Layer 3: 576 -> 288, K=5, Kcat=2880 =================
    convert_split_kernel<<<4096, 256>>>(acc2, F2, Ahi, Alo, KCAT3, 0);
    prop_kernel<F2><<<M_PAD, 128>>>(acc2, nullptr, bufA, Ahi, Alo, KCAT3, 1 * F2, 1.0f);
    prop_kernel<F2><<<M_PAD, 128>>>(bufA, acc2,    bufB, Ahi, Alo, KCAT3, 2 * F2, 2.0f);
    prop_kernel<F2><<<M_PAD, 128>>>(bufB, bufA,    bufC, Ahi, Alo, KCAT3, 3 * F2, 2.0f);
    prop_kernel<F2><<<M_PAD, 128>>>(bufC, bufB,    bufA, Ahi, Alo, KCAT3, 4 * F2, 2.0f);
    {
        dim3 grid(N3PAD / 128, M_PAD / 256);
        gemm_mma_kernel<<<grid, 256, SMEM_TOTAL_GEMM>>>(Ahi, Alo, W3h, W3l, b3, out, F3, KCAT3);
    }
}

// round 5
// speedup vs baseline: 1.0690x; 1.0690x over previous
#include <cuda_runtime.h>
#include <cuda_bf16.h>
#include <cstdint>
#include <cstddef>

#define N_NODES 20000
#define N_EDGES 320000
#define M_PAD   20224          // 158 * 128
#define F1 1152
#define F2 576
#define F3 288

#define KCAT1 (6 * F1)         // 6912
#define KCAT2 (5 * F1)         // 5760
#define KCAT3 (5 * F2)         // 2880
#define N1PAD 1152             // 9 * 128
#define N2PAD 640              // 5 * 128
#define N3PAD 384              // 3 * 128

// ---------------- scratch (device globals; allocation-free) ----------------
__device__ float g_bufA[N_NODES * F1];
__device__ float g_bufB[N_NODES * F1];
__device__ float g_bufC[N_NODES * F1];
__device__ float g_acc1[N_NODES * F1];
__device__ float g_acc2[N_NODES * F2];

__device__ __nv_bfloat16 g_Ahi[(size_t)M_PAD * KCAT1];
__device__ __nv_bfloat16 g_Alo[(size_t)M_PAD * KCAT1];
__device__ __nv_bfloat16 g_W1h[(size_t)N1PAD * KCAT1];
__device__ __nv_bfloat16 g_W1l[(size_t)N1PAD * KCAT1];
__device__ __nv_bfloat16 g_W2h[(size_t)N2PAD * KCAT2];
__device__ __nv_bfloat16 g_W2l[(size_t)N2PAD * KCAT2];
__device__ __nv_bfloat16 g_W3h[(size_t)N3PAD * KCAT3];
__device__ __nv_bfloat16 g_W3l[(size_t)N3PAD * KCAT3];

__device__ int   g_deg[N_NODES];
__device__ int   g_fill[N_NODES];
__device__ int   g_rowptr[N_NODES + 1];
__device__ int   g_colS[N_EDGES];
__device__ float g_dis[N_NODES];

// ---------------- PTX helpers (base sm_103 target only) ----------------
__device__ __forceinline__ uint32_t smem_u32(const void* p) {
    uint32_t a;
    asm("{ .reg .u64 t; cvta.to.shared.u64 t, %1; cvt.u32.u64 %0, t; }" : "=r"(a) : "l"(p));
    return a;
}

#define CP_ASYNC16(dst, src) \
    asm volatile("cp.async.cg.shared.global [%0], [%1], 16;" :: "r"(dst), "l"(src) : "memory")
#define CP_COMMIT() asm volatile("cp.async.commit_group;" ::: "memory")
#define CP_WAIT2()  asm volatile("cp.async.wait_group 2;" ::: "memory")

#define LDMATRIX_X4(r0, r1, r2, r3, addr) \
    asm volatile("ldmatrix.sync.aligned.m8n8.x4.shared.b16 {%0,%1,%2,%3}, [%4];" \
                 : "=r"(r0), "=r"(r1), "=r"(r2), "=r"(r3) : "r"(addr))

#define MMA_BF16(d, a, b) \
    asm volatile("mma.sync.aligned.m16n8k16.row.col.f32.bf16.bf16.f32 " \
                 "{%0,%1,%2,%3}, {%4,%5,%6,%7}, {%8,%9}, {%0,%1,%2,%3};" \
                 : "+f"((d)[0]), "+f"((d)[1]), "+f"((d)[2]), "+f"((d)[3]) \
                 : "r"((a)[0]), "r"((a)[1]), "r"((a)[2]), "r"((a)[3]), \
                   "r"((b)[0]), "r"((b)[1]))

// ---------------- graph setup ----------------
__global__ void zero_counts_kernel() {
    int i = blockIdx.x * blockDim.x + threadIdx.x;
    if (i < N_NODES) { g_deg[i] = 0; g_fill[i] = 0; }
}
__global__ void hist_kernel(const int* __restrict__ row, const int* __restrict__ col) {
    int e = blockIdx.x * blockDim.x + threadIdx.x;
    if (e < N_EDGES) {
        int r = row[e];
        if (r != col[e]) atomicAdd(&g_deg[r], 1);
    }
}
__global__ void scan_kernel() {
    __shared__ int sums[1024];
    int t = threadIdx.x;
    const int CHUNK = (N_NODES + 1023) / 1024;
    int lo = t * CHUNK, hi = lo + CHUNK;
    if (hi > N_NODES) hi = N_NODES;
    int s = 0;
    for (int i = lo; i < hi; i++) s += g_deg[i];
    sums[t] = s;
    __syncthreads();
    for (int off = 1; off < 1024; off <<= 1) {
        int v = (t >= off) ? sums[t - off] : 0;
        __syncthreads();
        sums[t] += v;
        __syncthreads();
    }
    int run = (t == 0) ? 0 : sums[t - 1];
    for (int i = lo; i < hi; i++) { g_rowptr[i] = run; run += g_deg[i]; }
    if (t == 1023) g_rowptr[N_NODES] = sums[1023];
}
__global__ void dis_kernel() {
    int i = blockIdx.x * blockDim.x + threadIdx.x;
    if (i < N_NODES) {
        int d = g_deg[i];
        g_dis[i] = (d > 0) ? rsqrtf((float)d) : 0.0f;
    }
}
__global__ void scatter_kernel(const int* __restrict__ row, const int* __restrict__ col) {
    int e = blockIdx.x * blockDim.x + threadIdx.x;
    if (e < N_EDGES) {
        int r = row[e], c = col[e];
        if (r != c) {
            int pos = g_rowptr[r] + atomicAdd(&g_fill[r], 1);
            g_colS[pos] = c;
        }
    }
}

// ---------------- split helpers ----------------
__device__ __forceinline__ void split1(float v, __nv_bfloat16& h, __nv_bfloat16& l) {
    h = __float2bfloat16(v);
    l = __float2bfloat16(v - __bfloat162float(h));
}

// convert Tx0 (fp32 [M x F]) into cat slice; zero pad rows
__global__ void convert_split_kernel(const float* __restrict__ src, int F,
                                     __nv_bfloat16* __restrict__ hi,
                                     __nv_bfloat16* __restrict__ lo,
                                     int ldCat, int colOff) {
    int total = M_PAD * F;
    for (int idx = blockIdx.x * blockDim.x + threadIdx.x; idx < total;
         idx += gridDim.x * blockDim.x) {
        int r = idx / F, c = idx - r * F;
        float v = (r < N_NODES) ? src[(size_t)r * F + c] : 0.0f;
        __nv_bfloat16 h, l;
        split1(v, h, l);
        size_t o = (size_t)r * ldCat + colOff + c;
        hi[o] = h; lo[o] = l;
    }
}

// weight transpose + split: W [Kcat x N] fp32 -> WT hi/lo [Npad x Kcat] bf16
__global__ void wsplit_kernel(const float* __restrict__ W, int Kcat, int N, int Npad,
                              __nv_bfloat16* __restrict__ hi,
                              __nv_bfloat16* __restrict__ lo) {
    __shared__ float tile[32][33];
    int k0 = blockIdx.x * 32, n0 = blockIdx.y * 32;
    int tx = threadIdx.x, ty = threadIdx.y;   // (32, 8)
#pragma unroll
    for (int r = 0; r < 32; r += 8) {
        int kk = k0 + ty + r, nn = n0 + tx;
        tile[ty + r][tx] = (kk < Kcat && nn < N) ? W[(size_t)kk * N + nn] : 0.0f;
    }
    __syncthreads();
#pragma unroll
    for (int r = 0; r < 32; r += 8) {
        int nn = n0 + ty + r, kk = k0 + tx;
        if (nn < Npad && kk < Kcat) {
            float v = tile[tx][ty + r];
            __nv_bfloat16 h, l;
            split1(v, h, l);
            hi[(size_t)nn * Kcat + kk] = h;
            lo[(size_t)nn * Kcat + kk] = l;
        }
    }
}

// ---------------- propagation with fused bf16 split of the output ----------
// out = alpha * (L~ t) - sub ; also writes hi/lo split into cat slice.
// THREADS chosen so NF = F/4/THREADS is an exact fit (no idle lanes).
template <int F, int THREADS>
__global__ void prop_kernel(const float* __restrict__ t,
                            const float* __restrict__ sub,
                            float* __restrict__ out,
                            __nv_bfloat16* __restrict__ hi,
                            __nv_bfloat16* __restrict__ lo,
                            int ldCat, int colOff, float alpha) {
    constexpr int F4 = F / 4;
    constexpr int NF = F4 / THREADS;
    static_assert(NF * THREADS == F4, "exact fit required");
    int i = blockIdx.x;
    int tid = threadIdx.x;
    bool real = (i < N_NODES);
    int s0 = real ? g_rowptr[i] : 0;
    int s1 = real ? g_rowptr[i + 1] : 0;

    float ax[NF], ay[NF], az[NF], aw[NF];
#pragma unroll
    for (int j = 0; j < NF; j++) { ax[j] = 0.f; ay[j] = 0.f; az[j] = 0.f; aw[j] = 0.f; }

    int e = s0;
    for (; e + 2 <= s1; e += 2) {
        int c0 = g_colS[e], c1 = g_colS[e + 1];
        float w0 = g_dis[c0], w1 = g_dis[c1];
        const float4* t0 = reinterpret_cast<const float4*>(t) + (size_t)c0 * F4;
        const float4* t1 = reinterpret_cast<const float4*>(t) + (size_t)c1 * F4;
#pragma unroll
        for (int j = 0; j < NF; j++) {
            int f = tid + j * THREADS;
            float4 v0 = t0[f];
            float4 v1 = t1[f];
            ax[j] += w0 * v0.x + w1 * v1.x;
            ay[j] += w0 * v0.y + w1 * v1.y;
            az[j] += w0 * v0.z + w1 * v1.z;
            aw[j] += w0 * v0.w + w1 * v1.w;
        }
    }
    if (e < s1) {
        int c = g_colS[e];
        float s = g_dis[c];
        const float4* tr = reinterpret_cast<const float4*>(t) + (size_t)c * F4;
#pragma unroll
        for (int j = 0; j < NF; j++) {
            int f = tid + j * THREADS;
            float4 v = tr[f];
            ax[j] += s * v.x; ay[j] += s * v.y;
            az[j] += s * v.z; aw[j] += s * v.w;
        }
    }

    float sc = real ? (-alpha * g_dis[i]) : 0.0f;
    float4* orow = real ? (reinterpret_cast<float4*>(out) + (size_t)i * F4) : nullptr;
    const float4* srow = (real && sub)
        ? (reinterpret_cast<const float4*>(sub) + (size_t)i * F4) : nullptr;
#pragma unroll
    for (int j = 0; j < NF; j++) {
        int f = tid + j * THREADS;
        float4 r;
        r.x = sc * ax[j]; r.y = sc * ay[j]; r.z = sc * az[j]; r.w = sc * aw[j];
        if (srow) {
            float4 sv = srow[f];
            r.x -= sv.x; r.y -= sv.y; r.z -= sv.z; r.w -= sv.w;
        }
        if (orow) orow[f] = r;
        __nv_bfloat16 hx, lx, hy, ly, hz, lz, hw, lw;
        split1(r.x, hx, lx); split1(r.y, hy, ly);
        split1(r.z, hz, lz); split1(r.w, hw, lw);
        size_t o = (size_t)i * ldCat + colOff + (size_t)f * 4;
        __nv_bfloat162* hp = reinterpret_cast<__nv_bfloat162*>(hi + o);
        __nv_bfloat162* lp = reinterpret_cast<__nv_bfloat162*>(lo + o);
        hp[0] = __nv_bfloat162(hx, hy); hp[1] = __nv_bfloat162(hz, hw);
        lp[0] = __nv_bfloat162(lx, ly); lp[1] = __nv_bfloat162(lz, lw);
    }
}

// ---------------- mma.sync GEMM (128x128 CTA, 4 warps of 64x64) ----------------
// C[M x N] = relu( A x B^T + bias ), 3-pass bf16 split in one long K loop.
// A: [M_PAD x Kcat] bf16 row-major.  B: [Npad x Kcat] bf16 row-major (= W^T).
// 128 threads, 2 CTAs/SM, single __syncthreads per k-tile.
#define GSTAGES 4
#define GBK     32
#define ROWB    80                        // padded SMEM row bytes (stride 5 in 16B units)
#define ATILE_B (128 * ROWB)              // 10240
#define STG_B   (2 * ATILE_B)             // 20480 per stage (A then B)
#define SMEM_TOTAL_GEMM (GSTAGES * STG_B) // 81920

__global__ void __launch_bounds__(128, 2)
gemm_mma_kernel(const __nv_bfloat16* __restrict__ Ahi, const __nv_bfloat16* __restrict__ Alo,
                const __nv_bfloat16* __restrict__ Bhi, const __nv_bfloat16* __restrict__ Blo,
                const float* __restrict__ bias, float* __restrict__ C,
                int N, int Kcat) {
    extern __shared__ char smem[];
    uint32_t sb = smem_u32(smem);
    int tid = threadIdx.x;
    int lane = tid & 31;
    int wid = tid >> 5;
    int bm = blockIdx.y * 128;
    int bn = blockIdx.x * 128;

    const int kt = Kcat / GBK;         // k-tiles per pass
    const int NIT = 3 * kt;

    int wm = (wid & 1) * 64;           // warp M offset (2 warps cover 128)
    int wn = (wid >> 1) * 64;          // warp N offset (2 warps cover 128)

    float d[4][8][4];
#pragma unroll
    for (int i = 0; i < 4; i++)
#pragma unroll
        for (int j = 0; j < 8; j++)
#pragma unroll
            for (int q = 0; q < 4; q++) d[i][j][q] = 0.f;

    auto issue = [&](int it) {
        int pass = it / kt;
        int kk = (it - pass * kt) * GBK;
        const __nv_bfloat16* Ab = (pass == 1) ? Alo : Ahi;
        const __nv_bfloat16* Bb = (pass == 2) ? Blo : Bhi;
        int s = it & (GSTAGES - 1);
        uint32_t sA = sb + s * STG_B;
        uint32_t sB = sA + ATILE_B;
        const char* gA = (const char*)(Ab + (size_t)bm * Kcat + kk);
        const char* gB = (const char*)(Bb + (size_t)bn * Kcat + kk);
        size_t ld = (size_t)Kcat * 2;
        // A: 128 rows x 64B = 512 16B-chunks; 4 per thread (128 threads)
#pragma unroll
        for (int i = 0; i < 4; i++) {
            int v = tid + i * 128;
            int r = v >> 2, p = v & 3;
            CP_ASYNC16(sA + r * ROWB + p * 16, gA + (size_t)r * ld + p * 16);
        }
#pragma unroll
        for (int i = 0; i < 4; i++) {
            int v = tid + i * 128;
            int r = v >> 2, p = v & 3;
            CP_ASYNC16(sB + r * ROWB + p * 16, gB + (size_t)r * ld + p * 16);
        }
    };

    // prologue: fill 3 stages
#pragma unroll
    for (int it = 0; it < GSTAGES - 1; it++) { issue(it); CP_COMMIT(); }

    int lrow = lane & 15;              // ldmatrix row within 16
    int lcol = (lane >> 4) * 8;        // ldmatrix k-half select

    for (int it = 0; it < NIT; ++it) {
        CP_WAIT2();
        __syncthreads();   // single barrier per k-tile: stage `it` visible to all,
                           // and all warps done reading stage (it-1)%4 = (it+3)%4

        if (it + GSTAGES - 1 < NIT) issue(it + GSTAGES - 1);
        CP_COMMIT();

        int s = it & (GSTAGES - 1);
        uint32_t sA = sb + s * STG_B;
        uint32_t sB = sA + ATILE_B;

#pragma unroll
        for (int ks = 0; ks < GBK; ks += 16) {
            uint32_t a[4][4], b[8][2];
#pragma unroll
            for (int i = 0; i < 4; i++) {
                uint32_t addr = sA + (wm + i * 16 + lrow) * ROWB + (ks + lcol) * 2;
                LDMATRIX_X4(a[i][0], a[i][1], a[i][2], a[i][3], addr);
            }
#pragma unroll
            for (int jp = 0; jp < 4; jp++) {
                uint32_t q0, q1, q2, q3;
                uint32_t addr = sB + (wn + jp * 16 + lrow) * ROWB + (ks + lcol) * 2;
                LDMATRIX_X4(q0, q1, q2, q3, addr);
                b[2 * jp][0] = q0; b[2 * jp][1] = q2;
                b[2 * jp + 1][0] = q1; b[2 * jp + 1][1] = q3;
            }
#pragma unroll
            for (int i = 0; i < 4; i++)
#pragma unroll
                for (int j = 0; j < 8; j++)
                    MMA_BF16(d[i][j], a[i], b[j]);
        }
    }

    // epilogue: bias + relu, fp32 writes
    int gr = lane >> 2;
    int gc = (lane & 3) * 2;
#pragma unroll
    for (int i = 0; i < 4; i++) {
#pragma unroll
        for (int j = 0; j < 8; j++) {
            int colb = bn + wn + j * 8 + gc;
            if (colb >= N) continue;
            float b0 = bias[colb], b1 = bias[colb + 1];
            int row0 = bm + wm + i * 16 + gr;
            if (row0 < N_NODES) {
                float2 v;
                v.x = fmaxf(d[i][j][0] + b0, 0.f);
                v.y = fmaxf(d[i][j][1] + b1, 0.f);
                *reinterpret_cast<float2*>(&C[(size_t)row0 * N + colb]) = v;
            }
            int row1 = row0 + 8;
            if (row1 < N_NODES) {
                float2 v;
                v.x = fmaxf(d[i][j][2] + b0, 0.f);
                v.y = fmaxf(d[i][j][3] + b1, 0.f);
                *reinterpret_cast<float2*>(&C[(size_t)row1 * N + colb]) = v;
            }
        }
    }
}

// ---------------- host orchestration ----------------
extern "C" void kernel_launch(void* const* d_in, const int* in_sizes, int n_in,
                              void* d_out, int out_size) {
    const float* x   = (const float*)d_in[0];
    const int*   row = (const int*)d_in[1];
    const int*   col = (const int*)d_in[2];
    const float* W1  = (const float*)d_in[3];
    const float* b1  = (const float*)d_in[4];
    const float* W2  = (const float*)d_in[5];
    const float* b2  = (const float*)d_in[6];
    const float* W3  = (const float*)d_in[7];
    const float* b3  = (const float*)d_in[8];
    float* out = (float*)d_out;

    float *bufA, *bufB, *bufC, *acc1, *acc2;
    __nv_bfloat16 *Ahi, *Alo, *W1h, *W1l, *W2h, *W2l, *W3h, *W3l;
    cudaGetSymbolAddress((void**)&bufA, g_bufA);
    cudaGetSymbolAddress((void**)&bufB, g_bufB);
    cudaGetSymbolAddress((void**)&bufC, g_bufC);
    cudaGetSymbolAddress((void**)&acc1, g_acc1);
    cudaGetSymbolAddress((void**)&acc2, g_acc2);
    cudaGetSymbolAddress((void**)&Ahi, g_Ahi);
    cudaGetSymbolAddress((void**)&Alo, g_Alo);
    cudaGetSymbolAddress((void**)&W1h, g_W1h);
    cudaGetSymbolAddress((void**)&W1l, g_W1l);
    cudaGetSymbolAddress((void**)&W2h, g_W2h);
    cudaGetSymbolAddress((void**)&W2l, g_W2l);
    cudaGetSymbolAddress((void**)&W3h, g_W3h);
    cudaGetSymbolAddress((void**)&W3l, g_W3l);

    cudaFuncSetAttribute(gemm_mma_kernel,
                         cudaFuncAttributeMaxDynamicSharedMemorySize, SMEM_TOTAL_GEMM);

    // ---- graph setup ----
    zero_counts_kernel<<<(N_NODES + 255) / 256, 256>>>();
    hist_kernel<<<(N_EDGES + 255) / 256, 256>>>(row, col);
    scan_kernel<<<1, 1024>>>();
    dis_kernel<<<(N_NODES + 255) / 256, 256>>>();
    scatter_kernel<<<(N_EDGES + 255) / 256, 256>>>(row, col);

    // ---- weight conversions ----
    {
        dim3 g1((KCAT1 + 31) / 32, (N1PAD + 31) / 32);
        wsplit_kernel<<<g1, dim3(32, 8)>>>(W1, KCAT1, F1, N1PAD, W1h, W1l);
        dim3 g2((KCAT2 + 31) / 32, (N2PAD + 31) / 32);
        wsplit_kernel<<<g2, dim3(32, 8)>>>(W2, KCAT2, F2, N2PAD, W2h, W2l);
        dim3 g3((KCAT3 + 31) / 32, (N3PAD + 31) / 32);
        wsplit_kernel<<<g3, dim3(32, 8)>>>(W3, KCAT3, F3, N3PAD, W3h, W3l);
    }

    // ================= Layer 1: 1152 -> 1152, K=6, Kcat=6912 =================
    convert_split_kernel<<<4096, 256>>>(x, F1, Ahi, Alo, KCAT1, 0);
    prop_kernel<F1, 96><<<M_PAD, 96>>>(x,    nullptr, bufA, Ahi, Alo, KCAT1, 1 * F1, 1.0f);
    prop_kernel<F1, 96><<<M_PAD, 96>>>(bufA, x,       bufB, Ahi, Alo, KCAT1, 2 * F1, 2.0f);
    prop_kernel<F1, 96><<<M_PAD, 96>>>(bufB, bufA,    bufC, Ahi, Alo, KCAT1, 3 * F1, 2.0f);
    prop_kernel<F1, 96><<<M_PAD, 96>>>(bufC, bufB,    bufA, Ahi, Alo, KCAT1, 4 * F1, 2.0f);
    prop_kernel<F1, 96><<<M_PAD, 96>>>(bufA, bufC,    bufB, Ahi, Alo, KCAT1, 5 * F1, 2.0f);
    {
        dim3 grid(N1PAD / 128, M_PAD / 128);
        gemm_mma_kernel<<<grid, 128, SMEM_TOTAL_GEMM>>>(Ahi, Alo, W1h, W1l, b1, acc1, F1, KCAT1);
    }

    // ================= Layer 2: 1152 -> 576, K=5, Kcat=5760 =================
    convert_split_kernel<<<4096, 256>>>(acc1, F1, Ahi, Alo, KCAT2, 0);
    prop_kernel<F1, 96><<<M_PAD, 96>>>(acc1, nullptr, bufA, Ahi, Alo, KCAT2, 1 * F1, 1.0f);
    prop_kernel<F1, 96><<<M_PAD, 96>>>(bufA, acc1,    bufB, Ahi, Alo, KCAT2, 2 * F1, 2.0f);
    prop_kernel<F1, 96><<<M_PAD, 96>>>(bufB, bufA,    bufC, Ahi, Alo, KCAT2, 3 * F1, 2.0f);
    prop_kernel<F1, 96><<<M_PAD, 96>>>(bufC, bufB,    bufA, Ahi, Alo, KCAT2, 4 * F1, 2.0f);
    {
        dim3 grid(N2PAD / 128, M_PAD / 128);
        gemm_mma_kernel<<<grid, 128, SMEM_TOTAL_GEMM>>>(Ahi, Alo, W2h, W2l, b2, acc2, F2, KCAT2);
    }

    // ================= Layer 3: 576 -> 288, K=5, Kcat=2880 =================
    convert_split_kernel<<<4096, 256>>>(acc2, F2, Ahi, Alo, KCAT3, 0);
    prop_kernel<F2, 144><<<M_PAD, 144>>>(acc2, nullptr, bufA, Ahi, Alo, KCAT3, 1 * F2, 1.0f);
    prop_kernel<F2, 144><<<M_PAD, 144>>>(bufA, acc2,    bufB, Ahi, Alo, KCAT3, 2 * F2, 2.0f);
    prop_kernel<F2, 144><<<M_PAD, 144>>>(bufB, bufA,    bufC, Ahi, Alo, KCAT3, 3 * F2, 2.0f);
    prop_kernel<F2, 144><<<M_PAD, 144>>>(bufC, bufB,    bufA, Ahi, Alo, KCAT3, 4 * F2, 2.0f);
    {
        dim3 grid(N3PAD / 128, M_PAD / 128);
        gemm_mma_kernel<<<grid, 128, SMEM_TOTAL_GEMM>>>(Ahi, Alo, W3h, W3l, b3, out, F3, KCAT3);
    }
}

// round 6
// speedup vs baseline: 1.2050x; 1.1272x over previous
#include <cuda_runtime.h>
#include <cuda_bf16.h>
#include <cstdint>
#include <cstddef>

#define N_NODES 20000
#define N_EDGES 320000
#define M_PAD   20224          // 158 * 128
#define F1 1152
#define F2 576
#define F3 288

#define KCAT1 (6 * F1)         // 6912
#define KCAT2 (5 * F1)         // 5760
#define KCAT3 (5 * F2)         // 2880
#define N1PAD 1152             // 9 * 128
#define N2PAD 640              // 5 * 128
#define N3PAD 384              // 3 * 128

// ---------------- scratch (device globals; allocation-free) ----------------
__device__ float g_bufA[N_NODES * F1];
__device__ float g_bufB[N_NODES * F1];
__device__ float g_bufC[N_NODES * F1];
__device__ float g_acc1[N_NODES * F1];
__device__ float g_acc2[N_NODES * F2];

// ping-pong A-cat buffers (avoid GEMM read/write aliasing across layers)
__device__ __nv_bfloat16 g_AhiA[(size_t)M_PAD * KCAT1];
__device__ __nv_bfloat16 g_AloA[(size_t)M_PAD * KCAT1];
__device__ __nv_bfloat16 g_AhiB[(size_t)M_PAD * KCAT2];
__device__ __nv_bfloat16 g_AloB[(size_t)M_PAD * KCAT2];

__device__ __nv_bfloat16 g_W1h[(size_t)N1PAD * KCAT1];
__device__ __nv_bfloat16 g_W1l[(size_t)N1PAD * KCAT1];
__device__ __nv_bfloat16 g_W2h[(size_t)N2PAD * KCAT2];
__device__ __nv_bfloat16 g_W2l[(size_t)N2PAD * KCAT2];
__device__ __nv_bfloat16 g_W3h[(size_t)N3PAD * KCAT3];
__device__ __nv_bfloat16 g_W3l[(size_t)N3PAD * KCAT3];

__device__ int   g_deg[N_NODES];
__device__ int   g_fill[N_NODES];
__device__ int   g_rowptr[N_NODES + 1];
__device__ int   g_colS[N_EDGES];
__device__ float g_dis[N_NODES];

// ---------------- PTX helpers (base sm_103 target only) ----------------
__device__ __forceinline__ uint32_t smem_u32(const void* p) {
    uint32_t a;
    asm("{ .reg .u64 t; cvta.to.shared.u64 t, %1; cvt.u32.u64 %0, t; }" : "=r"(a) : "l"(p));
    return a;
}

#define CP_ASYNC16(dst, src) \
    asm volatile("cp.async.cg.shared.global [%0], [%1], 16;" :: "r"(dst), "l"(src) : "memory")
#define CP_COMMIT() asm volatile("cp.async.commit_group;" ::: "memory")
#define CP_WAIT1()  asm volatile("cp.async.wait_group 1;" ::: "memory")

#define LDMATRIX_X4(r0, r1, r2, r3, addr) \
    asm volatile("ldmatrix.sync.aligned.m8n8.x4.shared.b16 {%0,%1,%2,%3}, [%4];" \
                 : "=r"(r0), "=r"(r1), "=r"(r2), "=r"(r3) : "r"(addr))

#define MMA_BF16(d, a, b) \
    asm volatile("mma.sync.aligned.m16n8k16.row.col.f32.bf16.bf16.f32 " \
                 "{%0,%1,%2,%3}, {%4,%5,%6,%7}, {%8,%9}, {%0,%1,%2,%3};" \
                 : "+f"((d)[0]), "+f"((d)[1]), "+f"((d)[2]), "+f"((d)[3]) \
                 : "r"((a)[0]), "r"((a)[1]), "r"((a)[2]), "r"((a)[3]), \
                   "r"((b)[0]), "r"((b)[1]))

// ---------------- graph setup ----------------
__global__ void zero_counts_kernel() {
    int i = blockIdx.x * blockDim.x + threadIdx.x;
    if (i < N_NODES) { g_deg[i] = 0; g_fill[i] = 0; }
}
__global__ void hist_kernel(const int* __restrict__ row, const int* __restrict__ col) {
    int e = blockIdx.x * blockDim.x + threadIdx.x;
    if (e < N_EDGES) {
        int r = row[e];
        if (r != col[e]) atomicAdd(&g_deg[r], 1);
    }
}
__global__ void scan_kernel() {
    __shared__ int sums[1024];
    int t = threadIdx.x;
    const int CHUNK = (N_NODES + 1023) / 1024;
    int lo = t * CHUNK, hi = lo + CHUNK;
    if (hi > N_NODES) hi = N_NODES;
    int s = 0;
    for (int i = lo; i < hi; i++) s += g_deg[i];
    sums[t] = s;
    __syncthreads();
    for (int off = 1; off < 1024; off <<= 1) {
        int v = (t >= off) ? sums[t - off] : 0;
        __syncthreads();
        sums[t] += v;
        __syncthreads();
    }
    int run = (t == 0) ? 0 : sums[t - 1];
    for (int i = lo; i < hi; i++) { g_rowptr[i] = run; run += g_deg[i]; }
    if (t == 1023) g_rowptr[N_NODES] = sums[1023];
}
__global__ void dis_kernel() {
    int i = blockIdx.x * blockDim.x + threadIdx.x;
    if (i < N_NODES) {
        int d = g_deg[i];
        g_dis[i] = (d > 0) ? rsqrtf((float)d) : 0.0f;
    }
}
__global__ void scatter_kernel(const int* __restrict__ row, const int* __restrict__ col) {
    int e = blockIdx.x * blockDim.x + threadIdx.x;
    if (e < N_EDGES) {
        int r = row[e], c = col[e];
        if (r != c) {
            int pos = g_rowptr[r] + atomicAdd(&g_fill[r], 1);
            g_colS[pos] = c;
        }
    }
}

// ---------------- split helpers ----------------
__device__ __forceinline__ void split1(float v, __nv_bfloat16& h, __nv_bfloat16& l) {
    h = __float2bfloat16(v);
    l = __float2bfloat16(v - __bfloat162float(h));
}

// convert x (fp32 [M x F]) into cat slice 0; zero pad rows
__global__ void convert_split_kernel(const float* __restrict__ src, int F,
                                     __nv_bfloat16* __restrict__ hi,
                                     __nv_bfloat16* __restrict__ lo,
                                     int ldCat, int colOff) {
    int total = M_PAD * F;
    for (int idx = blockIdx.x * blockDim.x + threadIdx.x; idx < total;
         idx += gridDim.x * blockDim.x) {
        int r = idx / F, c = idx - r * F;
        float v = (r < N_NODES) ? src[(size_t)r * F + c] : 0.0f;
        __nv_bfloat16 h, l;
        split1(v, h, l);
        size_t o = (size_t)r * ldCat + colOff + c;
        hi[o] = h; lo[o] = l;
    }
}

// weight transpose + split: W [Kcat x N] fp32 -> WT hi/lo [Npad x Kcat] bf16
__global__ void wsplit_kernel(const float* __restrict__ W, int Kcat, int N, int Npad,
                              __nv_bfloat16* __restrict__ hi,
                              __nv_bfloat16* __restrict__ lo) {
    __shared__ float tile[32][33];
    int k0 = blockIdx.x * 32, n0 = blockIdx.y * 32;
    int tx = threadIdx.x, ty = threadIdx.y;   // (32, 8)
#pragma unroll
    for (int r = 0; r < 32; r += 8) {
        int kk = k0 + ty + r, nn = n0 + tx;
        tile[ty + r][tx] = (kk < Kcat && nn < N) ? W[(size_t)kk * N + nn] : 0.0f;
    }
    __syncthreads();
#pragma unroll
    for (int r = 0; r < 32; r += 8) {
        int nn = n0 + ty + r, kk = k0 + tx;
        if (nn < Npad && kk < Kcat) {
            float v = tile[tx][ty + r];
            __nv_bfloat16 h, l;
            split1(v, h, l);
            hi[(size_t)nn * Kcat + kk] = h;
            lo[(size_t)nn * Kcat + kk] = l;
        }
    }
}

// ---------------- propagation with fused bf16 split of the output ----------
// out = alpha * (L~ t) - sub ; also writes hi/lo split into cat slice.
// Edge cols+weights staged through SMEM to break dependent-load chains.
template <int F, int THREADS>
__global__ void prop_kernel(const float* __restrict__ t,
                            const float* __restrict__ sub,
                            float* __restrict__ out,
                            __nv_bfloat16* __restrict__ hi,
                            __nv_bfloat16* __restrict__ lo,
                            int ldCat, int colOff, float alpha) {
    constexpr int F4 = F / 4;
    constexpr int NF = F4 / THREADS;
    static_assert(NF * THREADS == F4, "exact fit required");
    constexpr int ECHUNK = 128;
    __shared__ int   s_col[ECHUNK];
    __shared__ float s_w[ECHUNK];

    int i = blockIdx.x;
    int tid = threadIdx.x;
    bool real = (i < N_NODES);
    int s0 = real ? g_rowptr[i] : 0;
    int s1 = real ? g_rowptr[i + 1] : 0;

    float ax[NF], ay[NF], az[NF], aw[NF];
#pragma unroll
    for (int j = 0; j < NF; j++) { ax[j] = 0.f; ay[j] = 0.f; az[j] = 0.f; aw[j] = 0.f; }

    int e = s0;
    while (e < s1) {
        int cnt = s1 - e; if (cnt > ECHUNK) cnt = ECHUNK;
        __syncthreads();
        for (int q = tid; q < cnt; q += THREADS) {
            int c = g_colS[e + q];
            s_col[q] = c;
            s_w[q] = g_dis[c];
        }
        __syncthreads();

        int q = 0;
        for (; q + 2 <= cnt; q += 2) {
            int c0 = s_col[q], c1 = s_col[q + 1];
            float w0 = s_w[q], w1 = s_w[q + 1];
            const float4* t0 = reinterpret_cast<const float4*>(t) + (size_t)c0 * F4;
            const float4* t1 = reinterpret_cast<const float4*>(t) + (size_t)c1 * F4;
#pragma unroll
            for (int j = 0; j < NF; j++) {
                int f = tid + j * THREADS;
                float4 v0 = t0[f];
                float4 v1 = t1[f];
                ax[j] += w0 * v0.x + w1 * v1.x;
                ay[j] += w0 * v0.y + w1 * v1.y;
                az[j] += w0 * v0.z + w1 * v1.z;
                aw[j] += w0 * v0.w + w1 * v1.w;
            }
        }
        if (q < cnt) {
            int c = s_col[q];
            float s = s_w[q];
            const float4* tr = reinterpret_cast<const float4*>(t) + (size_t)c * F4;
#pragma unroll
            for (int j = 0; j < NF; j++) {
                int f = tid + j * THREADS;
                float4 v = tr[f];
                ax[j] += s * v.x; ay[j] += s * v.y;
                az[j] += s * v.z; aw[j] += s * v.w;
            }
        }
        e += cnt;
    }

    float sc = real ? (-alpha * g_dis[i]) : 0.0f;
    float4* orow = real ? (reinterpret_cast<float4*>(out) + (size_t)i * F4) : nullptr;
    const float4* srow = (real && sub)
        ? (reinterpret_cast<const float4*>(sub) + (size_t)i * F4) : nullptr;
#pragma unroll
    for (int j = 0; j < NF; j++) {
        int f = tid + j * THREADS;
        float4 r;
        r.x = sc * ax[j]; r.y = sc * ay[j]; r.z = sc * az[j]; r.w = sc * aw[j];
        if (srow) {
            float4 sv = srow[f];
            r.x -= sv.x; r.y -= sv.y; r.z -= sv.z; r.w -= sv.w;
        }
        if (orow) orow[f] = r;
        __nv_bfloat16 hx, lx, hy, ly, hz, lz, hw, lw;
        split1(r.x, hx, lx); split1(r.y, hy, ly);
        split1(r.z, hz, lz); split1(r.w, hw, lw);
        size_t o = (size_t)i * ldCat + colOff + (size_t)f * 4;
        __nv_bfloat162* hp = reinterpret_cast<__nv_bfloat162*>(hi + o);
        __nv_bfloat162* lp = reinterpret_cast<__nv_bfloat162*>(lo + o);
        hp[0] = __nv_bfloat162(hx, hy); hp[1] = __nv_bfloat162(hz, hw);
        lp[0] = __nv_bfloat162(lx, ly); lp[1] = __nv_bfloat162(lz, lw);
    }
}

// ---------------- fused tri-product mma.sync GEMM ----------------
// C = relu( (Ahi+Alo) x (Bhi+Blo)^T + bias ), dropping Alo*Blo:
// per k-tile: d += Ahi*Bhi + Alo*Bhi + Ahi*Blo   (single K sweep).
// Also (optionally) writes the bf16 hi/lo split of C into the NEXT layer's
// A-cat slice 0 (nextHi/nextLo, leading dim ldNext), zero-filling pad rows.
// 128x128 CTA, 4 warps of 64x64, 2 stages x 4 tiles, 2 CTAs/SM.
#define GBK     32
#define ROWB    80                        // padded SMEM row bytes (16B-aligned)
#define TILE_B  (128 * ROWB)              // 10240
#define STG_B   (4 * TILE_B)              // 40960: Ahi, Alo, Bhi, Blo
#define SMEM_TOTAL_GEMM (2 * STG_B)       // 81920

__global__ void __launch_bounds__(128, 2)
gemm_fused_kernel(const __nv_bfloat16* __restrict__ Ahi, const __nv_bfloat16* __restrict__ Alo,
                  const __nv_bfloat16* __restrict__ Bhi, const __nv_bfloat16* __restrict__ Blo,
                  const float* __restrict__ bias, float* __restrict__ C,
                  int N, int Kcat,
                  __nv_bfloat16* __restrict__ nextHi, __nv_bfloat16* __restrict__ nextLo,
                  int ldNext) {
    extern __shared__ char smem[];
    uint32_t sb = smem_u32(smem);
    int tid = threadIdx.x;
    int lane = tid & 31;
    int wid = tid >> 5;
    int bm = blockIdx.y * 128;
    int bn = blockIdx.x * 128;

    const int kt = Kcat / GBK;

    int wm = (wid & 1) * 64;
    int wn = (wid >> 1) * 64;

    float d[4][8][4];
#pragma unroll
    for (int i = 0; i < 4; i++)
#pragma unroll
        for (int j = 0; j < 8; j++)
#pragma unroll
            for (int q = 0; q < 4; q++) d[i][j][q] = 0.f;

    size_t ld = (size_t)Kcat * 2;   // bytes per row
    auto issue = [&](int it) {
        int kk = it * GBK;
        int s = it & 1;
        uint32_t base = sb + s * STG_B;
        const char* src[4] = {
            (const char*)(Ahi + (size_t)bm * Kcat + kk),
            (const char*)(Alo + (size_t)bm * Kcat + kk),
            (const char*)(Bhi + (size_t)bn * Kcat + kk),
            (const char*)(Blo + (size_t)bn * Kcat + kk)
        };
#pragma unroll
        for (int tIdx = 0; tIdx < 4; tIdx++) {
            uint32_t dst = base + tIdx * TILE_B;
            const char* g = src[tIdx];
#pragma unroll
            for (int i = 0; i < 4; i++) {
                int v = tid + i * 128;
                int r = v >> 2, p = v & 3;
                CP_ASYNC16(dst + r * ROWB + p * 16, g + (size_t)r * ld + p * 16);
            }
        }
    };

    // prologue: fill both stages
    issue(0); CP_COMMIT();
    if (kt > 1) issue(1);
    CP_COMMIT();

    int lrow = lane & 15;
    int lcol = (lane >> 4) * 8;

    for (int it = 0; it < kt; ++it) {
        CP_WAIT1();
        __syncthreads();

        int s = it & 1;
        uint32_t sAh = sb + s * STG_B;
        uint32_t sAl = sAh + TILE_B;
        uint32_t sBh = sAh + 2 * TILE_B;
        uint32_t sBl = sAh + 3 * TILE_B;

#pragma unroll
        for (int ks = 0; ks < GBK; ks += 16) {
            uint32_t ah[4][4], al[4][4], bh[8][2], bl[8][2];
#pragma unroll
            for (int i = 0; i < 4; i++) {
                uint32_t addr = sAh + (wm + i * 16 + lrow) * ROWB + (ks + lcol) * 2;
                LDMATRIX_X4(ah[i][0], ah[i][1], ah[i][2], ah[i][3], addr);
            }
#pragma unroll
            for (int i = 0; i < 4; i++) {
                uint32_t addr = sAl + (wm + i * 16 + lrow) * ROWB + (ks + lcol) * 2;
                LDMATRIX_X4(al[i][0], al[i][1], al[i][2], al[i][3], addr);
            }
#pragma unroll
            for (int jp = 0; jp < 4; jp++) {
                uint32_t q0, q1, q2, q3;
                uint32_t addr = sBh + (wn + jp * 16 + lrow) * ROWB + (ks + lcol) * 2;
                LDMATRIX_X4(q0, q1, q2, q3, addr);
                bh[2 * jp][0] = q0; bh[2 * jp][1] = q2;
                bh[2 * jp + 1][0] = q1; bh[2 * jp + 1][1] = q3;
            }
#pragma unroll
            for (int jp = 0; jp < 4; jp++) {
                uint32_t q0, q1, q2, q3;
                uint32_t addr = sBl + (wn + jp * 16 + lrow) * ROWB + (ks + lcol) * 2;
                LDMATRIX_X4(q0, q1, q2, q3, addr);
                bl[2 * jp][0] = q0; bl[2 * jp][1] = q2;
                bl[2 * jp + 1][0] = q1; bl[2 * jp + 1][1] = q3;
            }
#pragma unroll
            for (int i = 0; i < 4; i++)
#pragma unroll
                for (int j = 0; j < 8; j++) {
                    MMA_BF16(d[i][j], ah[i], bh[j]);
                    MMA_BF16(d[i][j], al[i], bh[j]);
                    MMA_BF16(d[i][j], ah[i], bl[j]);
                }
        }

        __syncthreads();
        if (it + 2 < kt) issue(it + 2);
        CP_COMMIT();
    }

    // epilogue: bias + relu; fp32 write + optional bf16 hi/lo split for next layer
    int gr = lane >> 2;
    int gc = (lane & 3) * 2;
#pragma unroll
    for (int i = 0; i < 4; i++) {
#pragma unroll
        for (int j = 0; j < 8; j++) {
            int colb = bn + wn + j * 8 + gc;
            if (colb >= N) continue;
            float b0 = bias[colb], b1 = bias[colb + 1];
            int row0 = bm + wm + i * 16 + gr;
            int row1 = row0 + 8;

            bool ok0 = row0 < N_NODES;
            float v0x = ok0 ? fmaxf(d[i][j][0] + b0, 0.f) : 0.f;
            float v0y = ok0 ? fmaxf(d[i][j][1] + b1, 0.f) : 0.f;
            if (ok0) {
                float2 v; v.x = v0x; v.y = v0y;
                *reinterpret_cast<float2*>(&C[(size_t)row0 * N + colb]) = v;
            }
            if (nextHi) {
                __nv_bfloat16 hx, lx, hy, ly;
                split1(v0x, hx, lx); split1(v0y, hy, ly);
                size_t o = (size_t)row0 * ldNext + colb;
                *reinterpret_cast<__nv_bfloat162*>(nextHi + o) = __nv_bfloat162(hx, hy);
                *reinterpret_cast<__nv_bfloat162*>(nextLo + o) = __nv_bfloat162(lx, ly);
            }

            bool ok1 = row1 < N_NODES;
            float v1x = ok1 ? fmaxf(d[i][j][2] + b0, 0.f) : 0.f;
            float v1y = ok1 ? fmaxf(d[i][j][3] + b1, 0.f) : 0.f;
            if (ok1) {
                float2 v; v.x = v1x; v.y = v1y;
                *reinterpret_cast<float2*>(&C[(size_t)row1 * N + colb]) = v;
            }
            if (nextHi) {
                __nv_bfloat16 hx, lx, hy, ly;
                split1(v1x, hx, lx); split1(v1y, hy, ly);
                size_t o = (size_t)row1 * ldNext + colb;
                *reinterpret_cast<__nv_bfloat162*>(nextHi + o) = __nv_bfloat162(hx, hy);
                *reinterpret_cast<__nv_bfloat162*>(nextLo + o) = __nv_bfloat162(lx, ly);
            }
        }
    }
}

// ---------------- host orchestration ----------------
extern "C" void kernel_launch(void* const* d_in, const int* in_sizes, int n_in,
                              void* d_out, int out_size) {
    const float* x   = (const float*)d_in[0];
    const int*   row = (const int*)d_in[1];
    const int*   col = (const int*)d_in[2];
    const float* W1  = (const float*)d_in[3];
    const float* b1  = (const float*)d_in[4];
    const float* W2  = (const float*)d_in[5];
    const float* b2  = (const float*)d_in[6];
    const float* W3  = (const float*)d_in[7];
    const float* b3  = (const float*)d_in[8];
    float* out = (float*)d_out;

    float *bufA, *bufB, *bufC, *acc1, *acc2;
    __nv_bfloat16 *AhiA, *AloA, *AhiB, *AloB;
    __nv_bfloat16 *W1h, *W1l, *W2h, *W2l, *W3h, *W3l;
    cudaGetSymbolAddress((void**)&bufA, g_bufA);
    cudaGetSymbolAddress((void**)&bufB, g_bufB);
    cudaGetSymbolAddress((void**)&bufC, g_bufC);
    cudaGetSymbolAddress((void**)&acc1, g_acc1);
    cudaGetSymbolAddress((void**)&acc2, g_acc2);
    cudaGetSymbolAddress((void**)&AhiA, g_AhiA);
    cudaGetSymbolAddress((void**)&AloA, g_AloA);
    cudaGetSymbolAddress((void**)&AhiB, g_AhiB);
    cudaGetSymbolAddress((void**)&AloB, g_AloB);
    cudaGetSymbolAddress((void**)&W1h, g_W1h);
    cudaGetSymbolAddress((void**)&W1l, g_W1l);
    cudaGetSymbolAddress((void**)&W2h, g_W2h);
    cudaGetSymbolAddress((void**)&W2l, g_W2l);
    cudaGetSymbolAddress((void**)&W3h, g_W3h);
    cudaGetSymbolAddress((void**)&W3l, g_W3l);

    cudaFuncSetAttribute(gemm_fused_kernel,
                         cudaFuncAttributeMaxDynamicSharedMemorySize, SMEM_TOTAL_GEMM);

    // ---- graph setup ----
    zero_counts_kernel<<<(N_NODES + 255) / 256, 256>>>();
    hist_kernel<<<(N_EDGES + 255) / 256, 256>>>(row, col);
    scan_kernel<<<1, 1024>>>();
    dis_kernel<<<(N_NODES + 255) / 256, 256>>>();
    scatter_kernel<<<(N_EDGES + 255) / 256, 256>>>(row, col);

    // ---- weight conversions ----
    {
        dim3 g1((KCAT1 + 31) / 32, (N1PAD + 31) / 32);
        wsplit_kernel<<<g1, dim3(32, 8)>>>(W1, KCAT1, F1, N1PAD, W1h, W1l);
        dim3 g2((KCAT2 + 31) / 32, (N2PAD + 31) / 32);
        wsplit_kernel<<<g2, dim3(32, 8)>>>(W2, KCAT2, F2, N2PAD, W2h, W2l);
        dim3 g3((KCAT3 + 31) / 32, (N3PAD + 31) / 32);
        wsplit_kernel<<<g3, dim3(32, 8)>>>(W3, KCAT3, F3, N3PAD, W3h, W3l);
    }

    // ================= Layer 1: 1152 -> 1152, K=6, Kcat=6912 =================
    convert_split_kernel<<<4096, 256>>>(x, F1, AhiA, AloA, KCAT1, 0);
    prop_kernel<F1, 96><<<M_PAD, 96>>>(x,    nullptr, bufA, AhiA, AloA, KCAT1, 1 * F1, 1.0f);
    prop_kernel<F1, 96><<<M_PAD, 96>>>(bufA, x,       bufB, AhiA, AloA, KCAT1, 2 * F1, 2.0f);
    prop_kernel<F1, 96><<<M_PAD, 96>>>(bufB, bufA,    bufC, AhiA, AloA, KCAT1, 3 * F1, 2.0f);
    prop_kernel<F1, 96><<<M_PAD, 96>>>(bufC, bufB,    bufA, AhiA, AloA, KCAT1, 4 * F1, 2.0f);
    prop_kernel<F1, 96><<<M_PAD, 96>>>(bufA, bufC,    bufB, AhiA, AloA, KCAT1, 5 * F1, 2.0f);
    {
        dim3 grid(N1PAD / 128, M_PAD / 128);
        gemm_fused_kernel<<<grid, 128, SMEM_TOTAL_GEMM>>>(
            AhiA, AloA, W1h, W1l, b1, acc1, F1, KCAT1, AhiB, AloB, KCAT2);
    }

    // ================= Layer 2: 1152 -> 576, K=5, Kcat=5760 =================
    prop_kernel<F1, 96><<<M_PAD, 96>>>(acc1, nullptr, bufA, AhiB, AloB, KCAT2, 1 * F1, 1.0f);
    prop_kernel<F1, 96><<<M_PAD, 96>>>(bufA, acc1,    bufB, AhiB, AloB, KCAT2, 2 * F1, 2.0f);
    prop_kernel<F1, 96><<<M_PAD, 96>>>(bufB, bufA,    bufC, AhiB, AloB, KCAT2, 3 * F1, 2.0f);
    prop_kernel<F1, 96><<<M_PAD, 96>>>(bufC, bufB,    bufA, AhiB, AloB, KCAT2, 4 * F1, 2.0f);
    {
        dim3 grid(N2PAD / 128, M_PAD / 128);
        gemm_fused_kernel<<<grid, 128, SMEM_TOTAL_GEMM>>>(
            AhiB, AloB, W2h, W2l, b2, acc2, F2, KCAT2, AhiA, AloA, KCAT3);
    }

    // ================= Layer 3: 576 -> 288, K=5, Kcat=2880 =================
    prop_kernel<F2, 144><<<M_PAD, 144>>>(acc2, nullptr, bufA, AhiA, AloA, KCAT3, 1 * F2, 1.0f);
    prop_kernel<F2, 144><<<M_PAD, 144>>>(bufA, acc2,    bufB, AhiA, AloA, KCAT3, 2 * F2, 2.0f);
    prop_kernel<F2, 144><<<M_PAD, 144>>>(bufB, bufA,    bufC, AhiA, AloA, KCAT3, 3 * F2, 2.0f);
    prop_kernel<F2, 144><<<M_PAD, 144>>>(bufC, bufB,    bufA, AhiA, AloA, KCAT3, 4 * F2, 2.0f);
    {
        dim3 grid(N3PAD / 128, M_PAD / 128);
        gemm_fused_kernel<<<grid, 128, SMEM_TOTAL_GEMM>>>(
            AhiA, AloA, W3h, W3l, b3, out, F3, KCAT3, nullptr, nullptr, 0);
    }
}

// round 7
// speedup vs baseline: 1.3549x; 1.1244x over previous
#include <cuda_runtime.h>
#include <cuda_bf16.h>
#include <cstdint>
#include <cstddef>

#define N_NODES 20000
#define N_EDGES 320000
#define M_PAD   20224          // 158 * 128
#define F1 1152
#define F2 576
#define F3 288

#define KCAT1 (6 * F1)         // 6912
#define KCAT2 (5 * F1)         // 5760
#define KCAT3 (5 * F2)         // 2880
#define N1PAD 1152             // 9 * 128
#define N2PAD 640              // 5 * 128
#define N3PAD 384              // 3 * 128

// ---------------- scratch (device globals; allocation-free) ----------------
__device__ float g_bufA[N_NODES * F1];
__device__ float g_bufB[N_NODES * F1];
__device__ float g_bufC[N_NODES * F1];
__device__ float g_acc1[N_NODES * F1];
__device__ float g_acc2[N_NODES * F2];

// ping-pong A-cat buffers (avoid GEMM read/write aliasing across layers)
__device__ __nv_bfloat16 g_AhiA[(size_t)M_PAD * KCAT1];
__device__ __nv_bfloat16 g_AloA[(size_t)M_PAD * KCAT1];
__device__ __nv_bfloat16 g_AhiB[(size_t)M_PAD * KCAT2];
__device__ __nv_bfloat16 g_AloB[(size_t)M_PAD * KCAT2];

__device__ __nv_bfloat16 g_W1h[(size_t)N1PAD * KCAT1];
__device__ __nv_bfloat16 g_W1l[(size_t)N1PAD * KCAT1];
__device__ __nv_bfloat16 g_W2h[(size_t)N2PAD * KCAT2];
__device__ __nv_bfloat16 g_W2l[(size_t)N2PAD * KCAT2];
__device__ __nv_bfloat16 g_W3h[(size_t)N3PAD * KCAT3];
__device__ __nv_bfloat16 g_W3l[(size_t)N3PAD * KCAT3];

__device__ int   g_deg[N_NODES];
__device__ int   g_fill[N_NODES];
__device__ int   g_rowptr[N_NODES + 1];
__device__ int   g_colS[N_EDGES];
__device__ float g_dis[N_NODES];

// ---------------- PTX helpers (base sm_103 target only) ----------------
__device__ __forceinline__ uint32_t smem_u32(const void* p) {
    uint32_t a;
    asm("{ .reg .u64 t; cvta.to.shared.u64 t, %1; cvt.u32.u64 %0, t; }" : "=r"(a) : "l"(p));
    return a;
}

#define CP_ASYNC16(dst, src) \
    asm volatile("cp.async.cg.shared.global [%0], [%1], 16;" :: "r"(dst), "l"(src) : "memory")
#define CP_COMMIT() asm volatile("cp.async.commit_group;" ::: "memory")
#define CP_WAIT1()  asm volatile("cp.async.wait_group 1;" ::: "memory")

#define LDMATRIX_X4(r0, r1, r2, r3, addr) \
    asm volatile("ldmatrix.sync.aligned.m8n8.x4.shared.b16 {%0,%1,%2,%3}, [%4];" \
                 : "=r"(r0), "=r"(r1), "=r"(r2), "=r"(r3) : "r"(addr))

#define MMA_BF16(d, a, b) \
    asm volatile("mma.sync.aligned.m16n8k16.row.col.f32.bf16.bf16.f32 " \
                 "{%0,%1,%2,%3}, {%4,%5,%6,%7}, {%8,%9}, {%0,%1,%2,%3};" \
                 : "+f"((d)[0]), "+f"((d)[1]), "+f"((d)[2]), "+f"((d)[3]) \
                 : "r"((a)[0]), "r"((a)[1]), "r"((a)[2]), "r"((a)[3]), \
                   "r"((b)[0]), "r"((b)[1]))

// ---------------- graph setup ----------------
__global__ void zero_counts_kernel() {
    int i = blockIdx.x * blockDim.x + threadIdx.x;
    if (i < N_NODES) { g_deg[i] = 0; g_fill[i] = 0; }
}
__global__ void hist_kernel(const int* __restrict__ row, const int* __restrict__ col) {
    int e = blockIdx.x * blockDim.x + threadIdx.x;
    if (e < N_EDGES) {
        int r = row[e];
        if (r != col[e]) atomicAdd(&g_deg[r], 1);
    }
}
__global__ void scan_kernel() {
    __shared__ int sums[1024];
    int t = threadIdx.x;
    const int CHUNK = (N_NODES + 1023) / 1024;
    int lo = t * CHUNK, hi = lo + CHUNK;
    if (hi > N_NODES) hi = N_NODES;
    int s = 0;
    for (int i = lo; i < hi; i++) s += g_deg[i];
    sums[t] = s;
    __syncthreads();
    for (int off = 1; off < 1024; off <<= 1) {
        int v = (t >= off) ? sums[t - off] : 0;
        __syncthreads();
        sums[t] += v;
        __syncthreads();
    }
    int run = (t == 0) ? 0 : sums[t - 1];
    for (int i = lo; i < hi; i++) { g_rowptr[i] = run; run += g_deg[i]; }
    if (t == 1023) g_rowptr[N_NODES] = sums[1023];
}
__global__ void dis_kernel() {
    int i = blockIdx.x * blockDim.x + threadIdx.x;
    if (i < N_NODES) {
        int d = g_deg[i];
        g_dis[i] = (d > 0) ? rsqrtf((float)d) : 0.0f;
    }
}
__global__ void scatter_kernel(const int* __restrict__ row, const int* __restrict__ col) {
    int e = blockIdx.x * blockDim.x + threadIdx.x;
    if (e < N_EDGES) {
        int r = row[e], c = col[e];
        if (r != c) {
            int pos = g_rowptr[r] + atomicAdd(&g_fill[r], 1);
            g_colS[pos] = c;
        }
    }
}

// ---------------- split helpers ----------------
__device__ __forceinline__ void split1(float v, __nv_bfloat16& h, __nv_bfloat16& l) {
    h = __float2bfloat16(v);
    l = __float2bfloat16(v - __bfloat162float(h));
}

// weight transpose + split: W [Kcat x N] fp32 -> WT hi/lo [Npad x Kcat] bf16
__global__ void wsplit_kernel(const float* __restrict__ W, int Kcat, int N, int Npad,
                              __nv_bfloat16* __restrict__ hi,
                              __nv_bfloat16* __restrict__ lo) {
    __shared__ float tile[32][33];
    int k0 = blockIdx.x * 32, n0 = blockIdx.y * 32;
    int tx = threadIdx.x, ty = threadIdx.y;   // (32, 8)
#pragma unroll
    for (int r = 0; r < 32; r += 8) {
        int kk = k0 + ty + r, nn = n0 + tx;
        tile[ty + r][tx] = (kk < Kcat && nn < N) ? W[(size_t)kk * N + nn] : 0.0f;
    }
    __syncthreads();
#pragma unroll
    for (int r = 0; r < 32; r += 8) {
        int nn = n0 + ty + r, kk = k0 + tx;
        if (nn < Npad && kk < Kcat) {
            float v = tile[tx][ty + r];
            __nv_bfloat16 h, l;
            split1(v, h, l);
            hi[(size_t)nn * Kcat + kk] = h;
            lo[(size_t)nn * Kcat + kk] = l;
        }
    }
}

// ---------------- propagation with fused bf16 split of the output ----------
// out = alpha * (L~ t) - sub (out may be nullptr if unused downstream);
// writes hi/lo split into cat slice colOff; if selfColOff >= 0, also splits
// this block's own row of t into cat slice selfColOff (replaces the separate
// convert kernel for Tx0). Pad rows write zeros into all touched slices.
template <int F, int THREADS>
__global__ void prop_kernel(const float* __restrict__ t,
                            const float* __restrict__ sub,
                            float* __restrict__ out,
                            __nv_bfloat16* __restrict__ hi,
                            __nv_bfloat16* __restrict__ lo,
                            int ldCat, int colOff, float alpha, int selfColOff) {
    constexpr int F4 = F / 4;
    constexpr int NF = F4 / THREADS;
    static_assert(NF * THREADS == F4, "exact fit required");
    constexpr int ECHUNK = 128;
    __shared__ int   s_col[ECHUNK];
    __shared__ float s_w[ECHUNK];

    int i = blockIdx.x;
    int tid = threadIdx.x;
    bool real = (i < N_NODES);
    int s0 = real ? g_rowptr[i] : 0;
    int s1 = real ? g_rowptr[i + 1] : 0;

    float ax[NF], ay[NF], az[NF], aw[NF];
#pragma unroll
    for (int j = 0; j < NF; j++) { ax[j] = 0.f; ay[j] = 0.f; az[j] = 0.f; aw[j] = 0.f; }

    int e = s0;
    while (e < s1) {
        int cnt = s1 - e; if (cnt > ECHUNK) cnt = ECHUNK;
        __syncthreads();
        for (int q = tid; q < cnt; q += THREADS) {
            int c = g_colS[e + q];
            s_col[q] = c;
            s_w[q] = g_dis[c];
        }
        __syncthreads();

        int q = 0;
        for (; q + 2 <= cnt; q += 2) {
            int c0 = s_col[q], c1 = s_col[q + 1];
            float w0 = s_w[q], w1 = s_w[q + 1];
            const float4* t0 = reinterpret_cast<const float4*>(t) + (size_t)c0 * F4;
            const float4* t1 = reinterpret_cast<const float4*>(t) + (size_t)c1 * F4;
#pragma unroll
            for (int j = 0; j < NF; j++) {
                int f = tid + j * THREADS;
                float4 v0 = t0[f];
                float4 v1 = t1[f];
                ax[j] += w0 * v0.x + w1 * v1.x;
                ay[j] += w0 * v0.y + w1 * v1.y;
                az[j] += w0 * v0.z + w1 * v1.z;
                aw[j] += w0 * v0.w + w1 * v1.w;
            }
        }
        if (q < cnt) {
            int c = s_col[q];
            float s = s_w[q];
            const float4* tr = reinterpret_cast<const float4*>(t) + (size_t)c * F4;
#pragma unroll
            for (int j = 0; j < NF; j++) {
                int f = tid + j * THREADS;
                float4 v = tr[f];
                ax[j] += s * v.x; ay[j] += s * v.y;
                az[j] += s * v.z; aw[j] += s * v.w;
            }
        }
        e += cnt;
    }

    float sc = real ? (-alpha * g_dis[i]) : 0.0f;
    float4* orow = (real && out) ? (reinterpret_cast<float4*>(out) + (size_t)i * F4) : nullptr;
    const float4* srow = (real && sub)
        ? (reinterpret_cast<const float4*>(sub) + (size_t)i * F4) : nullptr;
#pragma unroll
    for (int j = 0; j < NF; j++) {
        int f = tid + j * THREADS;
        float4 r;
        r.x = sc * ax[j]; r.y = sc * ay[j]; r.z = sc * az[j]; r.w = sc * aw[j];
        if (srow) {
            float4 sv = srow[f];
            r.x -= sv.x; r.y -= sv.y; r.z -= sv.z; r.w -= sv.w;
        }
        if (orow) orow[f] = r;
        __nv_bfloat16 hx, lx, hy, ly, hz, lz, hw, lw;
        split1(r.x, hx, lx); split1(r.y, hy, ly);
        split1(r.z, hz, lz); split1(r.w, hw, lw);
        size_t o = (size_t)i * ldCat + colOff + (size_t)f * 4;
        __nv_bfloat162* hp = reinterpret_cast<__nv_bfloat162*>(hi + o);
        __nv_bfloat162* lp = reinterpret_cast<__nv_bfloat162*>(lo + o);
        hp[0] = __nv_bfloat162(hx, hy); hp[1] = __nv_bfloat162(hz, hw);
        lp[0] = __nv_bfloat162(lx, ly); lp[1] = __nv_bfloat162(lz, lw);
    }

    // fused Tx0 split (replaces convert kernel)
    if (selfColOff >= 0) {
        const float4* me = real ? (reinterpret_cast<const float4*>(t) + (size_t)i * F4) : nullptr;
#pragma unroll
        for (int j = 0; j < NF; j++) {
            int f = tid + j * THREADS;
            float4 v = me ? me[f] : make_float4(0.f, 0.f, 0.f, 0.f);
            __nv_bfloat16 hx, lx, hy, ly, hz, lz, hw, lw;
            split1(v.x, hx, lx); split1(v.y, hy, ly);
            split1(v.z, hz, lz); split1(v.w, hw, lw);
            size_t o = (size_t)i * ldCat + selfColOff + (size_t)f * 4;
            __nv_bfloat162* hp = reinterpret_cast<__nv_bfloat162*>(hi + o);
            __nv_bfloat162* lp = reinterpret_cast<__nv_bfloat162*>(lo + o);
            hp[0] = __nv_bfloat162(hx, hy); hp[1] = __nv_bfloat162(hz, hw);
            lp[0] = __nv_bfloat162(lx, ly); lp[1] = __nv_bfloat162(lz, lw);
        }
    }
}

// ---------------- fused tri-product mma.sync GEMM ----------------
// C = relu( (Ahi+Alo) x (Bhi+Blo)^T + bias ), dropping Alo*Blo:
// per k-tile: d += Ahi*Bhi + Alo*Bhi + Ahi*Blo   (single K sweep).
// 128x128 CTA, 4 warps of 64x64, 3 stages, XOR-swizzled SMEM (no padding),
// single __syncthreads per k-tile, 2 CTAs/SM.
// SMEM layout per tile: off(r,c16) = r*64 + ((c16 ^ ((r>>1)&3))*16).
#define GBK     32
#define TILE_B  (128 * 64)                // 8192
#define STG_B   (4 * TILE_B)              // 32768: Ahi, Alo, Bhi, Blo
#define SMEM_TOTAL_GEMM (3 * STG_B)       // 98304

__device__ __forceinline__ uint32_t sw_off(int r, int c16) {
    return (uint32_t)(r * 64 + ((c16 ^ ((r >> 1) & 3)) * 16));
}

__global__ void __launch_bounds__(128, 2)
gemm_fused_kernel(const __nv_bfloat16* __restrict__ Ahi, const __nv_bfloat16* __restrict__ Alo,
                  const __nv_bfloat16* __restrict__ Bhi, const __nv_bfloat16* __restrict__ Blo,
                  const float* __restrict__ bias, float* __restrict__ C,
                  int N, int Kcat,
                  __nv_bfloat16* __restrict__ nextHi, __nv_bfloat16* __restrict__ nextLo,
                  int ldNext) {
    extern __shared__ char smem[];
    uint32_t sb = smem_u32(smem);
    int tid = threadIdx.x;
    int lane = tid & 31;
    int wid = tid >> 5;
    int bm = blockIdx.y * 128;
    int bn = blockIdx.x * 128;

    const int kt = Kcat / GBK;

    int wm = (wid & 1) * 64;
    int wn = (wid >> 1) * 64;

    float d[4][8][4];
#pragma unroll
    for (int i = 0; i < 4; i++)
#pragma unroll
        for (int j = 0; j < 8; j++)
#pragma unroll
            for (int q = 0; q < 4; q++) d[i][j][q] = 0.f;

    size_t ld = (size_t)Kcat * 2;   // bytes per row
    auto issue = [&](int it) {
        int kk = it * GBK;
        int s = it % 3;
        uint32_t base = sb + s * STG_B;
        const char* src[4] = {
            (const char*)(Ahi + (size_t)bm * Kcat + kk),
            (const char*)(Alo + (size_t)bm * Kcat + kk),
            (const char*)(Bhi + (size_t)bn * Kcat + kk),
            (const char*)(Blo + (size_t)bn * Kcat + kk)
        };
#pragma unroll
        for (int tIdx = 0; tIdx < 4; tIdx++) {
            uint32_t dst = base + tIdx * TILE_B;
            const char* g = src[tIdx];
#pragma unroll
            for (int i = 0; i < 4; i++) {
                int v = tid + i * 128;
                int r = v >> 2, p = v & 3;
                CP_ASYNC16(dst + sw_off(r, p), g + (size_t)r * ld + p * 16);
            }
        }
    };

    // prologue: 2 stages in flight
    issue(0); CP_COMMIT();
    if (kt > 1) issue(1);
    CP_COMMIT();

    int lrow = lane & 15;
    int lcol = (lane >> 4) * 8;

    for (int it = 0; it < kt; ++it) {
        CP_WAIT1();
        __syncthreads();                    // stage it%3 ready & all warps past it-1

        if (it + 2 < kt) issue(it + 2);     // writes stage (it+2)%3 == (it-1)%3: safe
        CP_COMMIT();

        int s = it % 3;
        uint32_t sAh = sb + s * STG_B;
        uint32_t sAl = sAh + TILE_B;
        uint32_t sBh = sAh + 2 * TILE_B;
        uint32_t sBl = sAh + 3 * TILE_B;

#pragma unroll
        for (int ks = 0; ks < GBK; ks += 16) {
            int cch = (ks + lcol) >> 3;     // 16B chunk index in row
            uint32_t ah[4][4], al[4][4], bh[8][2], bl[8][2];
#pragma unroll
            for (int i = 0; i < 4; i++) {
                int rr = wm + i * 16 + lrow;
                LDMATRIX_X4(ah[i][0], ah[i][1], ah[i][2], ah[i][3], sAh + sw_off(rr, cch));
            }
#pragma unroll
            for (int i = 0; i < 4; i++) {
                int rr = wm + i * 16 + lrow;
                LDMATRIX_X4(al[i][0], al[i][1], al[i][2], al[i][3], sAl + sw_off(rr, cch));
            }
#pragma unroll
            for (int jp = 0; jp < 4; jp++) {
                int rr = wn + jp * 16 + lrow;
                uint32_t q0, q1, q2, q3;
                LDMATRIX_X4(q0, q1, q2, q3, sBh + sw_off(rr, cch));
                bh[2 * jp][0] = q0; bh[2 * jp][1] = q2;
                bh[2 * jp + 1][0] = q1; bh[2 * jp + 1][1] = q3;
            }
#pragma unroll
            for (int jp = 0; jp < 4; jp++) {
                int rr = wn + jp * 16 + lrow;
                uint32_t q0, q1, q2, q3;
                LDMATRIX_X4(q0, q1, q2, q3, sBl + sw_off(rr, cch));
                bl[2 * jp][0] = q0; bl[2 * jp][1] = q2;
                bl[2 * jp + 1][0] = q1; bl[2 * jp + 1][1] = q3;
            }
#pragma unroll
            for (int i = 0; i < 4; i++)
#pragma unroll
                for (int j = 0; j < 8; j++) {
                    MMA_BF16(d[i][j], ah[i], bh[j]);
                    MMA_BF16(d[i][j], al[i], bh[j]);
                    MMA_BF16(d[i][j], ah[i], bl[j]);
                }
        }
    }

    // epilogue: bias + relu; fp32 write + optional bf16 hi/lo split for next layer
    int gr = lane >> 2;
    int gc = (lane & 3) * 2;
#pragma unroll
    for (int i = 0; i < 4; i++) {
#pragma unroll
        for (int j = 0; j < 8; j++) {
            int colb = bn + wn + j * 8 + gc;
            if (colb >= N) continue;
            float b0 = bias[colb], b1 = bias[colb + 1];
            int row0 = bm + wm + i * 16 + gr;
            int row1 = row0 + 8;

            bool ok0 = row0 < N_NODES;
            float v0x = ok0 ? fmaxf(d[i][j][0] + b0, 0.f) : 0.f;
            float v0y = ok0 ? fmaxf(d[i][j][1] + b1, 0.f) : 0.f;
            if (ok0) {
                float2 v; v.x = v0x; v.y = v0y;
                *reinterpret_cast<float2*>(&C[(size_t)row0 * N + colb]) = v;
            }
            if (nextHi) {
                __nv_bfloat16 hx, lx, hy, ly;
                split1(v0x, hx, lx); split1(v0y, hy, ly);
                size_t o = (size_t)row0 * ldNext + colb;
                *reinterpret_cast<__nv_bfloat162*>(nextHi + o) = __nv_bfloat162(hx, hy);
                *reinterpret_cast<__nv_bfloat162*>(nextLo + o) = __nv_bfloat162(lx, ly);
            }

            bool ok1 = row1 < N_NODES;
            float v1x = ok1 ? fmaxf(d[i][j][2] + b0, 0.f) : 0.f;
            float v1y = ok1 ? fmaxf(d[i][j][3] + b1, 0.f) : 0.f;
            if (ok1) {
                float2 v; v.x = v1x; v.y = v1y;
                *reinterpret_cast<float2*>(&C[(size_t)row1 * N + colb]) = v;
            }
            if (nextHi) {
                __nv_bfloat16 hx, lx, hy, ly;
                split1(v1x, hx, lx); split1(v1y, hy, ly);
                size_t o = (size_t)row1 * ldNext + colb;
                *reinterpret_cast<__nv_bfloat162*>(nextHi + o) = __nv_bfloat162(hx, hy);
                *reinterpret_cast<__nv_bfloat162*>(nextLo + o) = __nv_bfloat162(lx, ly);
            }
        }
    }
}

// ---------------- host orchestration ----------------
extern "C" void kernel_launch(void* const* d_in, const int* in_sizes, int n_in,
                              void* d_out, int out_size) {
    const float* x   = (const float*)d_in[0];
    const int*   row = (const int*)d_in[1];
    const int*   col = (const int*)d_in[2];
    const float* W1  = (const float*)d_in[3];
    const float* b1  = (const float*)d_in[4];
    const float* W2  = (const float*)d_in[5];
    const float* b2  = (const float*)d_in[6];
    const float* W3  = (const float*)d_in[7];
    const float* b3  = (const float*)d_in[8];
    float* out = (float*)d_out;

    float *bufA, *bufB, *bufC, *acc1, *acc2;
    __nv_bfloat16 *AhiA, *AloA, *AhiB, *AloB;
    __nv_bfloat16 *W1h, *W1l, *W2h, *W2l, *W3h, *W3l;
    cudaGetSymbolAddress((void**)&bufA, g_bufA);
    cudaGetSymbolAddress((void**)&bufB, g_bufB);
    cudaGetSymbolAddress((void**)&bufC, g_bufC);
    cudaGetSymbolAddress((void**)&acc1, g_acc1);
    cudaGetSymbolAddress((void**)&acc2, g_acc2);
    cudaGetSymbolAddress((void**)&AhiA, g_AhiA);
    cudaGetSymbolAddress((void**)&AloA, g_AloA);
    cudaGetSymbolAddress((void**)&AhiB, g_AhiB);
    cudaGetSymbolAddress((void**)&AloB, g_AloB);
    cudaGetSymbolAddress((void**)&W1h, g_W1h);
    cudaGetSymbolAddress((void**)&W1l, g_W1l);
    cudaGetSymbolAddress((void**)&W2h, g_W2h);
    cudaGetSymbolAddress((void**)&W2l, g_W2l);
    cudaGetSymbolAddress((void**)&W3h, g_W3h);
    cudaGetSymbolAddress((void**)&W3l, g_W3l);

    cudaFuncSetAttribute(gemm_fused_kernel,
                         cudaFuncAttributeMaxDynamicSharedMemorySize, SMEM_TOTAL_GEMM);

    // ---- graph setup (5 launches; 6th launch = F1 prop for ncu visibility) ----
    zero_counts_kernel<<<(N_NODES + 255) / 256, 256>>>();
    hist_kernel<<<(N_EDGES + 255) / 256, 256>>>(row, col);
    scan_kernel<<<1, 1024>>>();
    dis_kernel<<<(N_NODES + 255) / 256, 256>>>();
    scatter_kernel<<<(N_EDGES + 255) / 256, 256>>>(row, col);

    // ================= Layer 1: 1152 -> 1152, K=6, Kcat=6912 =================
    // prop1 also splits x itself into slice 0 (selfColOff = 0)
    prop_kernel<F1, 96><<<M_PAD, 96>>>(x,    nullptr, bufA, AhiA, AloA, KCAT1, 1 * F1, 1.0f, 0);
    prop_kernel<F1, 96><<<M_PAD, 96>>>(bufA, x,       bufB, AhiA, AloA, KCAT1, 2 * F1, 2.0f, -1);
    prop_kernel<F1, 96><<<M_PAD, 96>>>(bufB, bufA,    bufC, AhiA, AloA, KCAT1, 3 * F1, 2.0f, -1);
    prop_kernel<F1, 96><<<M_PAD, 96>>>(bufC, bufB,    bufA, AhiA, AloA, KCAT1, 4 * F1, 2.0f, -1);
    prop_kernel<F1, 96><<<M_PAD, 96>>>(bufA, bufC,    nullptr, AhiA, AloA, KCAT1, 5 * F1, 2.0f, -1);

    // ---- weight conversions (before first GEMM) ----
    {
        dim3 g1((KCAT1 + 31) / 32, (N1PAD + 31) / 32);
        wsplit_kernel<<<g1, dim3(32, 8)>>>(W1, KCAT1, F1, N1PAD, W1h, W1l);
        dim3 g2((KCAT2 + 31) / 32, (N2PAD + 31) / 32);
        wsplit_kernel<<<g2, dim3(32, 8)>>>(W2, KCAT2, F2, N2PAD, W2h, W2l);
        dim3 g3((KCAT3 + 31) / 32, (N3PAD + 31) / 32);
        wsplit_kernel<<<g3, dim3(32, 8)>>>(W3, KCAT3, F3, N3PAD, W3h, W3l);
    }

    {
        dim3 grid(N1PAD / 128, M_PAD / 128);
        gemm_fused_kernel<<<grid, 128, SMEM_TOTAL_GEMM>>>(
            AhiA, AloA, W1h, W1l, b1, acc1, F1, KCAT1, AhiB, AloB, KCAT2);
    }

    // ================= Layer 2: 1152 -> 576, K=5, Kcat=5760 =================
    prop_kernel<F1, 96><<<M_PAD, 96>>>(acc1, nullptr, bufA, AhiB, AloB, KCAT2, 1 * F1, 1.0f, -1);
    prop_kernel<F1, 96><<<M_PAD, 96>>>(bufA, acc1,    bufB, AhiB, AloB, KCAT2, 2 * F1, 2.0f, -1);
    prop_kernel<F1, 96><<<M_PAD, 96>>>(bufB, bufA,    bufC, AhiB, AloB, KCAT2, 3 * F1, 2.0f, -1);
    prop_kernel<F1, 96><<<M_PAD, 96>>>(bufC, bufB,    nullptr, AhiB, AloB, KCAT2, 4 * F1, 2.0f, -1);
    {
        dim3 grid(N2PAD / 128, M_PAD / 128);
        gemm_fused_kernel<<<grid, 128, SMEM_TOTAL_GEMM>>>(
            AhiB, AloB, W2h, W2l, b2, acc2, F2, KCAT2, AhiA, AloA, KCAT3);
    }

    // ================= Layer 3: 576 -> 288, K=5, Kcat=2880 =================
    prop_kernel<F2, 144><<<M_PAD, 144>>>(acc2, nullptr, bufA, AhiA, AloA, KCAT3, 1 * F2, 1.0f, -1);
    prop_kernel<F2, 144><<<M_PAD, 144>>>(bufA, acc2,    bufB, AhiA, AloA, KCAT3, 2 * F2, 2.0f, -1);
    prop_kernel<F2, 144><<<M_PAD, 144>>>(bufB, bufA,    bufC, AhiA, AloA, KCAT3, 3 * F2, 2.0f, -1);
    prop_kernel<F2, 144><<<M_PAD, 144>>>(bufC, bufB,    nullptr, AhiA, AloA, KCAT3, 4 * F2, 2.0f, -1);
    {
        dim3 grid(N3PAD / 128, M_PAD / 128);
        gemm_fused_kernel<<<grid, 128, SMEM_TOTAL_GEMM>>>(
            AhiA, AloA, W3h, W3l, b3, out, F3, KCAT3, nullptr, nullptr, 0);
    }
}